// round 3
// baseline (speedup 1.0000x reference)
#include <cuda_runtime.h>
#include <cstdint>

#define NTOK 4096
#define C_DIM 3072
#define F_DIM 12288
#define NB 32
#define BM_ 128
#define MBM_ 16
#define MBS 256
#define KSEL 1536

// ---------------- scratch ----------------
__device__ float g_bmx[MBS * C_DIM];
__device__ float g_bmfc1[MBS * F_DIM];
__device__ float g_mdiff[NB * F_DIM];
__device__ int   g_inds[NB * KSEL];
__device__ float g_delta[(size_t)NB * KSEL * BM_];  // [blk][ch][token]  (transposed!)

// ---------------- helpers ----------------
__device__ __forceinline__ uint32_t f2tf(float x) {
    uint32_t u;
    asm("cvt.rna.tf32.f32 %0, %1;" : "=r"(u) : "f"(x));
    return u;
}
__device__ __forceinline__ void mma_tf32(float c[4], const uint32_t a[4], const uint32_t b[2]) {
    asm volatile(
        "mma.sync.aligned.m16n8k8.row.col.f32.tf32.tf32.f32 "
        "{%0,%1,%2,%3},{%4,%5,%6,%7},{%8,%9},{%0,%1,%2,%3};"
        : "+f"(c[0]), "+f"(c[1]), "+f"(c[2]), "+f"(c[3])
        : "r"(a[0]), "r"(a[1]), "r"(a[2]), "r"(a[3]), "r"(b[0]), "r"(b[1]));
}
__device__ __forceinline__ float gelu_t(float v) {
    return 0.5f * v * (1.f + tanhf(0.7978845608028654f * (v + 0.044715f * v * v * v)));
}

// ---------------- kernel 1: block means ----------------
__global__ void k_bmean(const float* __restrict__ x) {
    int mb = blockIdx.x;
    int c  = blockIdx.y * 512 + threadIdx.x;
    const float* p = x + (size_t)mb * MBM_ * C_DIM + c;
    float s = 0.f;
#pragma unroll
    for (int t = 0; t < MBM_; t++) s += p[(size_t)t * C_DIM];
    g_bmx[mb * C_DIM + c] = s * (1.f / 16.f);
}

// ---------------- kernel 2: selection GEMM, 3xTF32 (fp32-accurate) ----------------
// C[m=256][n=12288] = bm_x @ fc1w^T + b, K=3072. Tile 128x128, BK=16.
#define SEL_ST 20
__global__ __launch_bounds__(256) void k_gemm_sel(const float* __restrict__ fc1w,
                                                  const float* __restrict__ fc1b) {
    __shared__ uint32_t Ah[128 * SEL_ST], Al[128 * SEL_ST];
    __shared__ uint32_t Bh[128 * SEL_ST], Bl[128 * SEL_ST];
    const int m0 = blockIdx.y * 128, n0 = blockIdx.x * 128;
    const int tid = threadIdx.x, wid = tid >> 5, lane = tid & 31;
    const int wm = wid & 1, wn = wid >> 1;       // warp tile 64x32
    const int grp = lane >> 2, tig = lane & 3;

    float acc[4][4][4];
#pragma unroll
    for (int i = 0; i < 4; i++)
#pragma unroll
        for (int j = 0; j < 4; j++)
#pragma unroll
            for (int q = 0; q < 4; q++) acc[i][j][q] = 0.f;

    float4 ra[2], rb[2];
    const int lrow = tid >> 2, lc4 = tid & 3;
#pragma unroll
    for (int r = 0; r < 2; r++) {
        int row = lrow + 64 * r;
        ra[r] = *(const float4*)(g_bmx + (size_t)(m0 + row) * C_DIM + lc4 * 4);
        rb[r] = *(const float4*)(fc1w + (size_t)(n0 + row) * C_DIM + lc4 * 4);
    }

    for (int k0 = 0; k0 < C_DIM; k0 += 16) {
#pragma unroll
        for (int r = 0; r < 2; r++) {
            int row = lrow + 64 * r;
            int base = row * SEL_ST + lc4 * 4;
            float av[4] = {ra[r].x, ra[r].y, ra[r].z, ra[r].w};
            float bv[4] = {rb[r].x, rb[r].y, rb[r].z, rb[r].w};
#pragma unroll
            for (int i = 0; i < 4; i++) {
                uint32_t h = f2tf(av[i]);
                Ah[base + i] = h;
                Al[base + i] = f2tf(av[i] - __uint_as_float(h));
                h = f2tf(bv[i]);
                Bh[base + i] = h;
                Bl[base + i] = f2tf(bv[i] - __uint_as_float(h));
            }
        }
        __syncthreads();
        if (k0 + 16 < C_DIM) {
#pragma unroll
            for (int r = 0; r < 2; r++) {
                int row = lrow + 64 * r;
                ra[r] = *(const float4*)(g_bmx + (size_t)(m0 + row) * C_DIM + k0 + 16 + lc4 * 4);
                rb[r] = *(const float4*)(fc1w + (size_t)(n0 + row) * C_DIM + k0 + 16 + lc4 * 4);
            }
        }
#pragma unroll
        for (int ks = 0; ks < 2; ks++) {
            const int kk = ks * 8;
            uint32_t ah[4][4], al[4][4], bh[4][2], bl[4][2];
#pragma unroll
            for (int mt = 0; mt < 4; mt++) {
                int mr = wm * 64 + mt * 16 + grp;
                ah[mt][0] = Ah[mr * SEL_ST + kk + tig];
                ah[mt][1] = Ah[(mr + 8) * SEL_ST + kk + tig];
                ah[mt][2] = Ah[mr * SEL_ST + kk + tig + 4];
                ah[mt][3] = Ah[(mr + 8) * SEL_ST + kk + tig + 4];
                al[mt][0] = Al[mr * SEL_ST + kk + tig];
                al[mt][1] = Al[(mr + 8) * SEL_ST + kk + tig];
                al[mt][2] = Al[mr * SEL_ST + kk + tig + 4];
                al[mt][3] = Al[(mr + 8) * SEL_ST + kk + tig + 4];
            }
#pragma unroll
            for (int nt = 0; nt < 4; nt++) {
                int nb = wn * 32 + nt * 8 + grp;
                bh[nt][0] = Bh[nb * SEL_ST + kk + tig];
                bh[nt][1] = Bh[nb * SEL_ST + kk + tig + 4];
                bl[nt][0] = Bl[nb * SEL_ST + kk + tig];
                bl[nt][1] = Bl[nb * SEL_ST + kk + tig + 4];
            }
#pragma unroll
            for (int mt = 0; mt < 4; mt++)
#pragma unroll
                for (int nt = 0; nt < 4; nt++) {
                    mma_tf32(acc[mt][nt], ah[mt], bl[nt]);
                    mma_tf32(acc[mt][nt], al[mt], bh[nt]);
                    mma_tf32(acc[mt][nt], ah[mt], bh[nt]);
                }
        }
        __syncthreads();
    }
#pragma unroll
    for (int mt = 0; mt < 4; mt++)
#pragma unroll
        for (int nt = 0; nt < 4; nt++) {
            int row = m0 + wm * 64 + mt * 16 + grp;
            int col = n0 + wn * 32 + nt * 8 + tig * 2;
            float b0 = fc1b[col], b1 = fc1b[col + 1];
            float2 o;
            o.x = acc[mt][nt][0] + b0; o.y = acc[mt][nt][1] + b1;
            *(float2*)(g_bmfc1 + (size_t)row * F_DIM + col) = o;
            o.x = acc[mt][nt][2] + b0; o.y = acc[mt][nt][3] + b1;
            *(float2*)(g_bmfc1 + (size_t)(row + 8) * F_DIM + col) = o;
        }
}

// ---------------- kernel 3: mdiff ----------------
__global__ void k_mdiff(const float* __restrict__ cache) {
    int b = blockIdx.y;
    int f = blockIdx.x * 256 + threadIdx.x;
    float s = 0.f;
#pragma unroll
    for (int r = 0; r < 8; r++) {
        size_t idx = (size_t)(b * 8 + r) * F_DIM + f;
        s += fabsf(g_bmfc1[idx] - cache[idx]);
    }
    g_mdiff[b * F_DIM + f] = s;
}

// ---------------- kernel 4: parallel top-1536 (radix select, 1024 threads) ----------------
__global__ __launch_bounds__(1024) void k_topk() {
    const int b = blockIdx.x, tid = threadIdx.x;
    const int lane = tid & 31, w = tid >> 5;
    const float* v = g_mdiff + (size_t)b * F_DIM;
    const int f0 = tid * 12;
    float vals[12];
#pragma unroll
    for (int j = 0; j < 12; j++) vals[j] = v[f0 + j];

    __shared__ int hist[256];
    __shared__ unsigned pref_s;
    __shared__ int rem_s;
    __shared__ int wsum[32];
    __shared__ int total_s;

    unsigned pref = 0;
    int rem = KSEL;
    for (int pass = 0; pass < 4; pass++) {
        const int sh = 24 - 8 * pass;
        if (tid < 256) hist[tid] = 0;
        __syncthreads();
#pragma unroll
        for (int j = 0; j < 12; j++) {
            unsigned u = __float_as_uint(vals[j]);
            if (pass == 0 || (u >> (sh + 8)) == pref)
                atomicAdd(&hist[(u >> sh) & 255], 1);
        }
        __syncthreads();
        // suffix sums over hist (Hillis-Steele)
        for (int off = 1; off < 256; off <<= 1) {
            int x_;
            if (tid < 256) x_ = hist[tid] + ((tid + off < 256) ? hist[tid + off] : 0);
            __syncthreads();
            if (tid < 256) hist[tid] = x_;
            __syncthreads();
        }
        if (tid < 256) {
            int nxt = (tid == 255) ? 0 : hist[tid + 1];
            if (hist[tid] >= rem && nxt < rem) {
                pref_s = (pref << 8) | (unsigned)tid;
                rem_s = rem - nxt;
            }
        }
        __syncthreads();
        pref = pref_s;
        rem = rem_s;
        __syncthreads();
    }

    // counts
    int cgt = 0, ceq = 0;
#pragma unroll
    for (int j = 0; j < 12; j++) {
        unsigned u = __float_as_uint(vals[j]);
        if (u > pref) cgt++;
        else if (u == pref) ceq++;
    }
    // exclusive scan of cgt
    int inc = cgt;
#pragma unroll
    for (int off = 1; off < 32; off <<= 1) {
        int n_ = __shfl_up_sync(0xffffffffu, inc, off);
        if (lane >= off) inc += n_;
    }
    if (lane == 31) wsum[w] = inc;
    __syncthreads();
    if (w == 0) {
        int t = wsum[lane];
#pragma unroll
        for (int off = 1; off < 32; off <<= 1) {
            int n_ = __shfl_up_sync(0xffffffffu, t, off);
            if (lane >= off) t += n_;
        }
        wsum[lane] = t;
    }
    __syncthreads();
    int base = (w > 0 ? wsum[w - 1] : 0) + inc - cgt;
    if (tid == 1023) total_s = base + cgt;
    __syncthreads();
    const int total_gt = total_s;
    {
        int pos = base;
#pragma unroll
        for (int j = 0; j < 12; j++)
            if (__float_as_uint(vals[j]) > pref) g_inds[b * KSEL + (pos++)] = f0 + j;
    }
    __syncthreads();
    // exclusive scan of ceq
    inc = ceq;
#pragma unroll
    for (int off = 1; off < 32; off <<= 1) {
        int n_ = __shfl_up_sync(0xffffffffu, inc, off);
        if (lane >= off) inc += n_;
    }
    if (lane == 31) wsum[w] = inc;
    __syncthreads();
    if (w == 0) {
        int t = wsum[lane];
#pragma unroll
        for (int off = 1; off < 32; off <<= 1) {
            int n_ = __shfl_up_sync(0xffffffffu, t, off);
            if (lane >= off) t += n_;
        }
        wsum[lane] = t;
    }
    __syncthreads();
    int ebase = (w > 0 ? wsum[w - 1] : 0) + inc - ceq;
    const int need = KSEL - total_gt;
#pragma unroll
    for (int j = 0; j < 12; j++)
        if (__float_as_uint(vals[j]) == pref) {
            if (ebase < need) g_inds[b * KSEL + total_gt + ebase] = f0 + j;
            ebase++;
        }
}

// ---------------- kernel 5: gathered fc1 GEMM (tf32) + gelu + delta (transposed out) ----------
// C[m=ch(128)][n=token(128)] = fc1w[inds] @ x_blk^T; K=3072, BK=32.
#define G1_ST 36
__global__ __launch_bounds__(256) void k_gemm1(const float* __restrict__ x,
                                               const float* __restrict__ fc1w,
                                               const float* __restrict__ fc1b,
                                               const float* __restrict__ sAT) {
    __shared__ uint32_t As[128 * G1_ST];   // gathered w1, m(ch)-major
    __shared__ uint32_t Bs[128 * G1_ST];   // x tile, n(token)-major
    __shared__ int ridx[128];
    __shared__ float bsh[128];
    const int blk = blockIdx.y, mchunk = blockIdx.x;
    const int tid = threadIdx.x, wid = tid >> 5, lane = tid & 31;
    const int wm = wid & 1, wn = wid >> 1;
    const int grp = lane >> 2, tig = lane & 3;

    if (tid < 128) {
        int id = g_inds[blk * KSEL + mchunk * 128 + tid];
        ridx[tid] = id;
        bsh[tid] = fc1b[id];
    }
    __syncthreads();

    float acc[4][4][4];
#pragma unroll
    for (int i = 0; i < 4; i++)
#pragma unroll
        for (int j = 0; j < 4; j++)
#pragma unroll
            for (int q = 0; q < 4; q++) acc[i][j][q] = 0.f;

    const float* xb = x + (size_t)blk * BM_ * C_DIM;
    const int lrow = tid >> 3, lc4 = tid & 7;
    float4 ra[4], rb[4];
#pragma unroll
    for (int r = 0; r < 4; r++) {
        int row = lrow + 32 * r;
        ra[r] = *(const float4*)(fc1w + (size_t)ridx[row] * C_DIM + lc4 * 4);
        rb[r] = *(const float4*)(xb + (size_t)row * C_DIM + lc4 * 4);
    }

    for (int k0 = 0; k0 < C_DIM; k0 += 32) {
#pragma unroll
        for (int r = 0; r < 4; r++) {
            int row = lrow + 32 * r;
            int base = row * G1_ST + lc4 * 4;
            As[base + 0] = f2tf(ra[r].x); As[base + 1] = f2tf(ra[r].y);
            As[base + 2] = f2tf(ra[r].z); As[base + 3] = f2tf(ra[r].w);
            Bs[base + 0] = f2tf(rb[r].x); Bs[base + 1] = f2tf(rb[r].y);
            Bs[base + 2] = f2tf(rb[r].z); Bs[base + 3] = f2tf(rb[r].w);
        }
        __syncthreads();
        if (k0 + 32 < C_DIM) {
#pragma unroll
            for (int r = 0; r < 4; r++) {
                int row = lrow + 32 * r;
                ra[r] = *(const float4*)(fc1w + (size_t)ridx[row] * C_DIM + k0 + 32 + lc4 * 4);
                rb[r] = *(const float4*)(xb + (size_t)row * C_DIM + k0 + 32 + lc4 * 4);
            }
        }
#pragma unroll
        for (int ks = 0; ks < 4; ks++) {
            const int kk = ks * 8;
            uint32_t af[4][4], bf[4][2];
#pragma unroll
            for (int mt = 0; mt < 4; mt++) {
                int mr = wm * 64 + mt * 16 + grp;
                af[mt][0] = As[mr * G1_ST + kk + tig];
                af[mt][1] = As[(mr + 8) * G1_ST + kk + tig];
                af[mt][2] = As[mr * G1_ST + kk + tig + 4];
                af[mt][3] = As[(mr + 8) * G1_ST + kk + tig + 4];
            }
#pragma unroll
            for (int nt = 0; nt < 4; nt++) {
                int nb = wn * 32 + nt * 8 + grp;
                bf[nt][0] = Bs[nb * G1_ST + kk + tig];
                bf[nt][1] = Bs[nb * G1_ST + kk + tig + 4];
            }
#pragma unroll
            for (int mt = 0; mt < 4; mt++)
#pragma unroll
                for (int nt = 0; nt < 4; nt++) mma_tf32(acc[mt][nt], af[mt], bf[nt]);
        }
        __syncthreads();
    }

    // epilogue: gelu(acc + b) - cached -> g_delta[blk][ch][token]
#pragma unroll
    for (int mt = 0; mt < 4; mt++)
#pragma unroll
        for (int nt = 0; nt < 4; nt++) {
            int t0 = wn * 32 + nt * 8 + tig * 2;
#pragma unroll
            for (int half = 0; half < 2; half++) {
                int r = wm * 64 + mt * 16 + grp + 8 * half;
                float bb = bsh[r];
                int chg = ridx[r];
                const float* cp = sAT + (size_t)chg * NTOK + blk * BM_ + t0;
                float2 cached = *(const float2*)cp;
                float v0 = acc[mt][nt][half * 2 + 0] + bb;
                float v1 = acc[mt][nt][half * 2 + 1] + bb;
                float2 o;
                o.x = gelu_t(v0) - cached.x;
                o.y = gelu_t(v1) - cached.y;
                *(float2*)(g_delta + ((size_t)blk * KSEL + mchunk * 128 + r) * BM_ + t0) = o;
            }
        }
}

// ---------------- kernel 6: gathered fc2 GEMM (tf32) + out_cache add ----------------
// C[m=token(128)][n=cdim(128)] ; K=1536, A=deltaT k-major, B=gathered fc2wT k-major.
#define G2_ST 136
__global__ __launch_bounds__(256) void k_gemm2(const float* __restrict__ fc2wT,
                                               const float* __restrict__ out_cache,
                                               float* __restrict__ out) {
    __shared__ uint32_t As[32 * G2_ST];
    __shared__ uint32_t Bs[32 * G2_ST];
    __shared__ int kidx[KSEL];
    const int blk = blockIdx.y, n0 = blockIdx.x * 128;
    const int tid = threadIdx.x, wid = tid >> 5, lane = tid & 31;
    const int wm = wid & 1, wn = wid >> 1;
    const int grp = lane >> 2, tig = lane & 3;

    for (int i = tid; i < KSEL; i += 256) kidx[i] = g_inds[blk * KSEL + i];
    __syncthreads();

    float acc[4][4][4];
#pragma unroll
    for (int i = 0; i < 4; i++)
#pragma unroll
        for (int j = 0; j < 4; j++)
#pragma unroll
            for (int q = 0; q < 4; q++) acc[i][j][q] = 0.f;

    const float* Ab = g_delta + (size_t)blk * KSEL * BM_;
    float4 ra[4], rb[4];
#pragma unroll
    for (int r = 0; r < 4; r++) {
        int idx = tid + 256 * r;
        int ch = idx >> 5, t4 = idx & 31;
        ra[r] = *(const float4*)(Ab + (size_t)ch * BM_ + t4 * 4);
        rb[r] = *(const float4*)(fc2wT + (size_t)kidx[ch] * C_DIM + n0 + t4 * 4);
    }

    for (int k0 = 0; k0 < KSEL; k0 += 32) {
#pragma unroll
        for (int r = 0; r < 4; r++) {
            int idx = tid + 256 * r;
            int ch = idx >> 5, t4 = idx & 31;
            int base = ch * G2_ST + t4 * 4;
            As[base + 0] = f2tf(ra[r].x); As[base + 1] = f2tf(ra[r].y);
            As[base + 2] = f2tf(ra[r].z); As[base + 3] = f2tf(ra[r].w);
            Bs[base + 0] = f2tf(rb[r].x); Bs[base + 1] = f2tf(rb[r].y);
            Bs[base + 2] = f2tf(rb[r].z); Bs[base + 3] = f2tf(rb[r].w);
        }
        __syncthreads();
        if (k0 + 32 < KSEL) {
#pragma unroll
            for (int r = 0; r < 4; r++) {
                int idx = tid + 256 * r;
                int ch = idx >> 5, t4 = idx & 31;
                ra[r] = *(const float4*)(Ab + (size_t)(k0 + 32 + ch) * BM_ + t4 * 4);
                rb[r] = *(const float4*)(fc2wT + (size_t)kidx[k0 + 32 + ch] * C_DIM + n0 + t4 * 4);
            }
        }
#pragma unroll
        for (int ks = 0; ks < 4; ks++) {
            const int kk = ks * 8;
            uint32_t af[4][4], bf[4][2];
#pragma unroll
            for (int mt = 0; mt < 4; mt++) {
                int mb = wm * 64 + mt * 16 + grp;
                af[mt][0] = As[(kk + tig) * G2_ST + mb];
                af[mt][1] = As[(kk + tig) * G2_ST + mb + 8];
                af[mt][2] = As[(kk + tig + 4) * G2_ST + mb];
                af[mt][3] = As[(kk + tig + 4) * G2_ST + mb + 8];
            }
#pragma unroll
            for (int nt = 0; nt < 4; nt++) {
                int nb = wn * 32 + nt * 8 + grp;
                bf[nt][0] = Bs[(kk + tig) * G2_ST + nb];
                bf[nt][1] = Bs[(kk + tig + 4) * G2_ST + nb];
            }
#pragma unroll
            for (int mt = 0; mt < 4; mt++)
#pragma unroll
                for (int nt = 0; nt < 4; nt++) mma_tf32(acc[mt][nt], af[mt], bf[nt]);
        }
        __syncthreads();
    }

#pragma unroll
    for (int mt = 0; mt < 4; mt++)
#pragma unroll
        for (int nt = 0; nt < 4; nt++) {
            int col = n0 + wn * 32 + nt * 8 + tig * 2;
#pragma unroll
            for (int half = 0; half < 2; half++) {
                int trow = wm * 64 + mt * 16 + grp + 8 * half;
                size_t off = (size_t)(blk * BM_ + trow) * C_DIM + col;
                float2 oc = *(const float2*)(out_cache + off);
                float2 o;
                o.x = oc.x + acc[mt][nt][half * 2 + 0];
                o.y = oc.y + acc[mt][nt][half * 2 + 1];
                *(float2*)(out + off) = o;
            }
        }
}

// ---------------- launch ----------------
extern "C" void kernel_launch(void* const* d_in, const int* in_sizes, int n_in,
                              void* d_out, int out_size) {
    const float* x     = (const float*)d_in[0];
    const float* fc1w  = (const float*)d_in[1];
    const float* fc1b  = (const float*)d_in[2];
    const float* fc2wT = (const float*)d_in[3];
    const float* bmc   = (const float*)d_in[4];
    const float* sAT   = (const float*)d_in[5];
    const float* outc  = (const float*)d_in[6];
    float* out = (float*)d_out;

    k_bmean<<<dim3(256, 6), 512>>>(x);
    k_gemm_sel<<<dim3(96, 2), 256>>>(fc1w, fc1b);
    k_mdiff<<<dim3(48, 32), 256>>>(bmc);
    k_topk<<<32, 1024>>>();
    k_gemm1<<<dim3(12, 32), 256>>>(x, fc1w, fc1b, sAT);
    k_gemm2<<<dim3(24, 32), 256>>>(fc2wT, outc, out);
}

// round 5
// speedup vs baseline: 1.4573x; 1.4573x over previous
#include <cuda_runtime.h>
#include <cstdint>

#if defined(__CUDA_ARCH_FEAT_SM103_ALL) || defined(__CUDA_ARCH_FEAT_SM100_ALL) || \
    (defined(__CUDA_ARCH_FAMILY_SPECIFIC__) && (__CUDA_ARCH_FAMILY_SPECIFIC__ >= 1000))
#define TC_OK 1
#else
#define TC_OK 0
#endif

#define NTOK 4096
#define C_DIM 3072
#define F_DIM 12288
#define NB 32
#define BM_ 128
#define MBM_ 16
#define MBS 256
#define KSEL 1536

// idesc: dtype F32(1<<4), atype TF32(2<<7), btype TF32(2<<10), N=128(16<<17), M=128(8<<24)
#define IDESC_TF32 ((1u<<4)|(2u<<7)|(2u<<10)|(16u<<17)|(8u<<24))
#define SWZ(o) ((o) ^ (((o) >> 3) & 0x70))

#define SEL_SMEM (8 * 16384 + 1024)
#define G_SMEM   (4 * 16384 + 1024)

// ---------------- scratch ----------------
__device__ float g_bmx[MBS * C_DIM];
__device__ float g_mdiff[NB * F_DIM];
__device__ int   g_inds[NB * KSEL];
__device__ float g_delta[(size_t)NB * BM_ * KSEL];

// ---------------- common helpers ----------------
__device__ __forceinline__ uint32_t f2tf(float x) {
    uint32_t u; asm("cvt.rna.tf32.f32 %0, %1;" : "=r"(u) : "f"(x)); return u;
}
__device__ __forceinline__ float gelu_t(float v) {
    return 0.5f * v * (1.f + tanhf(0.7978845608028654f * (v + 0.044715f * v * v * v)));
}
// legacy mma.sync (fallback path)
__device__ __forceinline__ void mma_frag(float c[4], const uint32_t a[4], const uint32_t b[2]) {
    asm volatile(
        "mma.sync.aligned.m16n8k8.row.col.f32.tf32.tf32.f32 "
        "{%0,%1,%2,%3},{%4,%5,%6,%7},{%8,%9},{%0,%1,%2,%3};"
        : "+f"(c[0]), "+f"(c[1]), "+f"(c[2]), "+f"(c[3])
        : "r"(a[0]), "r"(a[1]), "r"(a[2]), "r"(a[3]), "r"(b[0]), "r"(b[1]));
}

#if TC_OK
// ---------------- tcgen05 helpers (compiled only for arch-specific targets) --------------
__device__ __forceinline__ uint32_t sm32(const void* p) {
    uint32_t a;
    asm("{ .reg .u64 t; cvta.to.shared.u64 t, %1; cvt.u32.u64 %0, t; }" : "=r"(a) : "l"(p));
    return a;
}
__device__ __forceinline__ void mbar_init(uint32_t m, uint32_t c) {
    asm volatile("mbarrier.init.shared.b64 [%0], %1;" :: "r"(m), "r"(c) : "memory");
}
__device__ __forceinline__ void mbar_wait(uint32_t m, uint32_t par) {
    asm volatile(
        "{\n\t.reg .pred P;\n"
        "W_%=:\n\t"
        "mbarrier.try_wait.parity.acquire.cta.shared::cta.b64 P, [%0], %1, 0x989680;\n\t"
        "@!P bra.uni W_%=;\n\t}"
        :: "r"(m), "r"(par) : "memory");
}
__device__ __forceinline__ void tc_alloc(uint32_t slot, uint32_t n) {
    asm volatile("tcgen05.alloc.cta_group::1.sync.aligned.shared::cta.b32 [%0], %1;"
                 :: "r"(slot), "r"(n) : "memory");
}
__device__ __forceinline__ void tc_relinq() {
    asm volatile("tcgen05.relinquish_alloc_permit.cta_group::1.sync.aligned;");
}
__device__ __forceinline__ void tc_dealloc(uint32_t t, uint32_t n) {
    asm volatile("tcgen05.dealloc.cta_group::1.sync.aligned.b32 %0, %1;" :: "r"(t), "r"(n));
}
__device__ __forceinline__ void tc_commit(uint32_t m) {
    asm volatile("tcgen05.commit.cta_group::1.mbarrier::arrive::one.shared::cluster.b64 [%0];"
                 :: "r"(m) : "memory");
}
__device__ __forceinline__ void fence_async() {
    asm volatile("fence.proxy.async.shared::cta;" ::: "memory");
}
__device__ __forceinline__ void tc_fence_after() {
    asm volatile("tcgen05.fence::after_thread_sync;" ::: "memory");
}
__device__ __forceinline__ void tc_wait_ld() {
    asm volatile("tcgen05.wait::ld.sync.aligned;" ::: "memory");
}
__device__ __forceinline__ void mma_ss(uint32_t d, uint64_t a, uint64_t b, uint32_t en) {
    asm volatile(
        "{\n\t.reg .pred p;\n\t"
        "setp.ne.u32 p, %5, 0;\n\t"
        "tcgen05.mma.cta_group::1.kind::tf32 [%0], %1, %2, %3, {%4,%4,%4,%4}, p;\n\t}"
        :: "r"(d), "l"(a), "l"(b), "r"(IDESC_TF32), "r"(0u), "r"(en) : "memory");
}
__device__ __forceinline__ uint64_t mk_desc(uint32_t addr) {
    const uint64_t base = (uint64_t(2) << 61) | (uint64_t(1) << 46) |
                          (uint64_t(64) << 32) | (uint64_t(1) << 16);
    return base | ((uint64_t)(addr >> 4) & 0x3FFF);
}
#define TC_LD32(r, a) \
    asm volatile( \
        "tcgen05.ld.sync.aligned.32x32b.x32.b32 " \
        "{%0,%1,%2,%3,%4,%5,%6,%7,%8,%9,%10,%11,%12,%13,%14,%15," \
        "%16,%17,%18,%19,%20,%21,%22,%23,%24,%25,%26,%27,%28,%29,%30,%31}, [%32];" \
        : "=r"((r)[0]),"=r"((r)[1]),"=r"((r)[2]),"=r"((r)[3]),"=r"((r)[4]),"=r"((r)[5]), \
          "=r"((r)[6]),"=r"((r)[7]),"=r"((r)[8]),"=r"((r)[9]),"=r"((r)[10]),"=r"((r)[11]), \
          "=r"((r)[12]),"=r"((r)[13]),"=r"((r)[14]),"=r"((r)[15]),"=r"((r)[16]),"=r"((r)[17]), \
          "=r"((r)[18]),"=r"((r)[19]),"=r"((r)[20]),"=r"((r)[21]),"=r"((r)[22]),"=r"((r)[23]), \
          "=r"((r)[24]),"=r"((r)[25]),"=r"((r)[26]),"=r"((r)[27]),"=r"((r)[28]),"=r"((r)[29]), \
          "=r"((r)[30]),"=r"((r)[31]) : "r"(a))
#endif  // TC_OK

// ---------------- kernel 1: block means ----------------
__global__ void k_bmean(const float* __restrict__ x) {
    int mb = blockIdx.x;
    int c  = blockIdx.y * 512 + threadIdx.x;
    const float* p = x + (size_t)mb * MBM_ * C_DIM + c;
    float s = 0.f;
#pragma unroll
    for (int t = 0; t < MBM_; t++) s += p[(size_t)t * C_DIM];
    g_bmx[mb * C_DIM + c] = s * (1.f / 16.f);
}

// ---------------- kernel 2: selection GEMM (3xTF32) fused bias+|diff|+rsum --------------
// grid (96, 2): blockIdx.x = f-tile (128 of 12288), blockIdx.y = mb-tile (128 of 256).
// Writes g_mdiff[b][f] directly; g_bmfc1 eliminated.
__global__ __launch_bounds__(256) void k_sel(const float* __restrict__ fc1w,
                                             const float* __restrict__ fc1b,
                                             const float* __restrict__ bmc) {
    extern __shared__ char dsm[];
    char* base = (char*)((((uintptr_t)dsm) + 1023) & ~(uintptr_t)1023);
    const int tid = threadIdx.x, wid = tid >> 5, lane = tid & 31;

#if TC_OK
    // ---------------- tcgen05 path: D[f(128 lanes)][mb(128 cols)] ----------------
    __shared__ uint32_t s_tmem;
    __shared__ uint64_t s_mbar[2];
    const int m0 = blockIdx.x * 128, n0 = blockIdx.y * 128;
    const uint32_t sb = sm32(base);

    if (wid == 0) tc_alloc(sm32(&s_tmem), 128);
    if (tid == 0) { mbar_init(sm32(&s_mbar[0]), 1); mbar_init(sm32(&s_mbar[1]), 1); }
    __syncthreads();
    const uint32_t tmem = s_tmem;
    const uint32_t mb0 = sm32(&s_mbar[0]), mb1 = sm32(&s_mbar[1]);

    const int row = tid >> 3, c4 = tid & 7;
    float4 ra[4], rb[4];
#pragma unroll
    for (int r = 0; r < 4; r++) {
        int rr = row + 32 * r;
        ra[r] = *(const float4*)(fc1w + (size_t)(m0 + rr) * C_DIM + c4 * 4);
        rb[r] = *(const float4*)(g_bmx + (size_t)(n0 + rr) * C_DIM + c4 * 4);
    }
    const int NCH = C_DIM / 32;  // 96
    for (int i = 0; i < NCH; i++) {
        const int s = i & 1;
        if (i >= 2) mbar_wait(s ? mb1 : mb0, ((i >> 1) - 1) & 1);
        const uint32_t Ah = sb + (s * 4 + 0) * 16384, Al = sb + (s * 4 + 1) * 16384;
        const uint32_t Bh = sb + (s * 4 + 2) * 16384, Bl = sb + (s * 4 + 3) * 16384;
#pragma unroll
        for (int r = 0; r < 4; r++) {
            int rr = row + 32 * r;
            uint32_t off = SWZ(rr * 128 + c4 * 16);
            float av[4] = {ra[r].x, ra[r].y, ra[r].z, ra[r].w};
            float bv[4] = {rb[r].x, rb[r].y, rb[r].z, rb[r].w};
            uint4 h, l;
            h.x = f2tf(av[0]); l.x = f2tf(av[0] - __uint_as_float(h.x));
            h.y = f2tf(av[1]); l.y = f2tf(av[1] - __uint_as_float(h.y));
            h.z = f2tf(av[2]); l.z = f2tf(av[2] - __uint_as_float(h.z));
            h.w = f2tf(av[3]); l.w = f2tf(av[3] - __uint_as_float(h.w));
            *(uint4*)(base + (Ah - sb) + off) = h;
            *(uint4*)(base + (Al - sb) + off) = l;
            h.x = f2tf(bv[0]); l.x = f2tf(bv[0] - __uint_as_float(h.x));
            h.y = f2tf(bv[1]); l.y = f2tf(bv[1] - __uint_as_float(h.y));
            h.z = f2tf(bv[2]); l.z = f2tf(bv[2] - __uint_as_float(h.z));
            h.w = f2tf(bv[3]); l.w = f2tf(bv[3] - __uint_as_float(h.w));
            *(uint4*)(base + (Bh - sb) + off) = h;
            *(uint4*)(base + (Bl - sb) + off) = l;
        }
        fence_async();
        if (i + 1 < NCH) {
            int k0 = (i + 1) * 32;
#pragma unroll
            for (int r = 0; r < 4; r++) {
                int rr = row + 32 * r;
                ra[r] = *(const float4*)(fc1w + (size_t)(m0 + rr) * C_DIM + k0 + c4 * 4);
                rb[r] = *(const float4*)(g_bmx + (size_t)(n0 + rr) * C_DIM + k0 + c4 * 4);
            }
        }
        __syncthreads();
        if (tid == 0) {
            uint64_t dah = mk_desc(Ah), dal = mk_desc(Al);
            uint64_t dbh = mk_desc(Bh), dbl = mk_desc(Bl);
#pragma unroll
            for (int ks = 0; ks < 4; ks++) {
                mma_ss(tmem, dah + ks * 2, dbl + ks * 2, (i | ks) ? 1u : 0u);
                mma_ss(tmem, dal + ks * 2, dbh + ks * 2, 1u);
                mma_ss(tmem, dah + ks * 2, dbh + ks * 2, 1u);
            }
            tc_commit(s ? mb1 : mb0);
        }
    }
    mbar_wait(mb1, 1);  // chunk 95 -> buffer 1, use idx 47 -> parity 1
    tc_fence_after();
    const int subp = wid & 3, l = subp * 32 + lane;
    const int f = m0 + l;
    const float bias = fc1b[f];
    const int cb = (wid >> 2) * 64;
    float sum[8];
#pragma unroll
    for (int q = 0; q < 8; q++) sum[q] = 0.f;
#pragma unroll
    for (int g = 0; g < 2; g++) {
        uint32_t d[32];
        TC_LD32(d, tmem + cb + g * 32);
        tc_wait_ld();
#pragma unroll
        for (int j = 0; j < 32; j++) {
            int mbi = n0 + cb + g * 32 + j;
            float val = __uint_as_float(d[j]) + bias;
            sum[(g * 32 + j) >> 3] += fabsf(val - bmc[(size_t)mbi * F_DIM + f]);
        }
    }
    const int b0 = (n0 + cb) >> 3;
#pragma unroll
    for (int q = 0; q < 8; q++) g_mdiff[(size_t)(b0 + q) * F_DIM + f] = sum[q];
    __syncthreads();
    if (wid == 0) { tc_relinq(); tc_dealloc(tmem, 128); }

#else
    // ---------------- fallback: mma.sync 3xTF32, C[mb][f], fused mdiff epilogue ----------
    const int SEL_ST = 20;
    uint32_t* Ah = (uint32_t*)base;
    uint32_t* Al = Ah + 128 * SEL_ST;
    uint32_t* Bh = Al + 128 * SEL_ST;
    uint32_t* Bl = Bh + 128 * SEL_ST;
    float* S = (float*)(Bl + 128 * SEL_ST);   // 128 x 129 staging
    const int m0 = blockIdx.y * 128, n0 = blockIdx.x * 128;   // m = mb, n = f
    const int wm = wid & 1, wn = wid >> 1;
    const int grp = lane >> 2, tig = lane & 3;

    float acc[4][4][4];
#pragma unroll
    for (int i = 0; i < 4; i++)
#pragma unroll
        for (int j = 0; j < 4; j++)
#pragma unroll
            for (int q = 0; q < 4; q++) acc[i][j][q] = 0.f;

    float4 ra[2], rb[2];
    const int lrow = tid >> 2, lc4 = tid & 3;
#pragma unroll
    for (int r = 0; r < 2; r++) {
        int rrow = lrow + 64 * r;
        ra[r] = *(const float4*)(g_bmx + (size_t)(m0 + rrow) * C_DIM + lc4 * 4);
        rb[r] = *(const float4*)(fc1w + (size_t)(n0 + rrow) * C_DIM + lc4 * 4);
    }
    for (int k0 = 0; k0 < C_DIM; k0 += 16) {
#pragma unroll
        for (int r = 0; r < 2; r++) {
            int rrow = lrow + 64 * r;
            int bidx = rrow * SEL_ST + lc4 * 4;
            float av[4] = {ra[r].x, ra[r].y, ra[r].z, ra[r].w};
            float bv[4] = {rb[r].x, rb[r].y, rb[r].z, rb[r].w};
#pragma unroll
            for (int i = 0; i < 4; i++) {
                uint32_t h = f2tf(av[i]);
                Ah[bidx + i] = h;
                Al[bidx + i] = f2tf(av[i] - __uint_as_float(h));
                h = f2tf(bv[i]);
                Bh[bidx + i] = h;
                Bl[bidx + i] = f2tf(bv[i] - __uint_as_float(h));
            }
        }
        __syncthreads();
        if (k0 + 16 < C_DIM) {
#pragma unroll
            for (int r = 0; r < 2; r++) {
                int rrow = lrow + 64 * r;
                ra[r] = *(const float4*)(g_bmx + (size_t)(m0 + rrow) * C_DIM + k0 + 16 + lc4 * 4);
                rb[r] = *(const float4*)(fc1w + (size_t)(n0 + rrow) * C_DIM + k0 + 16 + lc4 * 4);
            }
        }
#pragma unroll
        for (int ks = 0; ks < 2; ks++) {
            const int kk = ks * 8;
            uint32_t ah[4][4], al[4][4], bh[4][2], bl[4][2];
#pragma unroll
            for (int mt = 0; mt < 4; mt++) {
                int mr = wm * 64 + mt * 16 + grp;
                ah[mt][0] = Ah[mr * SEL_ST + kk + tig];
                ah[mt][1] = Ah[(mr + 8) * SEL_ST + kk + tig];
                ah[mt][2] = Ah[mr * SEL_ST + kk + tig + 4];
                ah[mt][3] = Ah[(mr + 8) * SEL_ST + kk + tig + 4];
                al[mt][0] = Al[mr * SEL_ST + kk + tig];
                al[mt][1] = Al[(mr + 8) * SEL_ST + kk + tig];
                al[mt][2] = Al[mr * SEL_ST + kk + tig + 4];
                al[mt][3] = Al[(mr + 8) * SEL_ST + kk + tig + 4];
            }
#pragma unroll
            for (int nt = 0; nt < 4; nt++) {
                int nb = wn * 32 + nt * 8 + grp;
                bh[nt][0] = Bh[nb * SEL_ST + kk + tig];
                bh[nt][1] = Bh[nb * SEL_ST + kk + tig + 4];
                bl[nt][0] = Bl[nb * SEL_ST + kk + tig];
                bl[nt][1] = Bl[nb * SEL_ST + kk + tig + 4];
            }
#pragma unroll
            for (int mt = 0; mt < 4; mt++)
#pragma unroll
                for (int nt = 0; nt < 4; nt++) {
                    mma_frag(acc[mt][nt], ah[mt], bl[nt]);
                    mma_frag(acc[mt][nt], al[mt], bh[nt]);
                    mma_frag(acc[mt][nt], ah[mt], bh[nt]);
                }
        }
        __syncthreads();
    }
    // stage D^T into smem: S[f_local][mb_local]
#pragma unroll
    for (int mt = 0; mt < 4; mt++)
#pragma unroll
        for (int nt = 0; nt < 4; nt++) {
            int m_l = wm * 64 + mt * 16 + grp;
            int n_l = wn * 32 + nt * 8 + tig * 2;
            S[n_l * 129 + m_l]           = acc[mt][nt][0];
            S[(n_l + 1) * 129 + m_l]     = acc[mt][nt][1];
            S[n_l * 129 + m_l + 8]       = acc[mt][nt][2];
            S[(n_l + 1) * 129 + m_l + 8] = acc[mt][nt][3];
        }
    __syncthreads();
    const int f_l = tid & 127, gh = tid >> 7;
    const int fg = n0 + f_l;
    const float bias = fc1b[fg];
#pragma unroll
    for (int q = 0; q < 8; q++) {
        int mb_l0 = (gh * 8 + q) * 8;
        float s = 0.f;
#pragma unroll
        for (int t = 0; t < 8; t++)
            s += fabsf(S[f_l * 129 + mb_l0 + t] + bias -
                       bmc[(size_t)(m0 + mb_l0 + t) * F_DIM + fg]);
        g_mdiff[(size_t)((m0 + mb_l0) >> 3) * F_DIM + fg] = s;
    }
#endif
}

// ---------------- kernel 3: parallel top-1536 (radix select) ----------------
__global__ __launch_bounds__(1024) void k_topk() {
    const int b = blockIdx.x, tid = threadIdx.x;
    const int lane = tid & 31, w = tid >> 5;
    const float* v = g_mdiff + (size_t)b * F_DIM;
    const int f0 = tid * 12;
    float vals[12];
#pragma unroll
    for (int j = 0; j < 12; j++) vals[j] = v[f0 + j];

    __shared__ int hist[256];
    __shared__ unsigned pref_s;
    __shared__ int rem_s;
    __shared__ int wsum[32];
    __shared__ int total_s;

    unsigned pref = 0;
    int rem = KSEL;
    for (int pass = 0; pass < 4; pass++) {
        const int sh = 24 - 8 * pass;
        if (tid < 256) hist[tid] = 0;
        __syncthreads();
#pragma unroll
        for (int j = 0; j < 12; j++) {
            unsigned u = __float_as_uint(vals[j]);
            if (pass == 0 || (u >> (sh + 8)) == pref)
                atomicAdd(&hist[(u >> sh) & 255], 1);
        }
        __syncthreads();
        for (int off = 1; off < 256; off <<= 1) {
            int x_;
            if (tid < 256) x_ = hist[tid] + ((tid + off < 256) ? hist[tid + off] : 0);
            __syncthreads();
            if (tid < 256) hist[tid] = x_;
            __syncthreads();
        }
        if (tid < 256) {
            int nxt = (tid == 255) ? 0 : hist[tid + 1];
            if (hist[tid] >= rem && nxt < rem) {
                pref_s = (pref << 8) | (unsigned)tid;
                rem_s = rem - nxt;
            }
        }
        __syncthreads();
        pref = pref_s;
        rem = rem_s;
        __syncthreads();
    }
    int cgt = 0, ceq = 0;
#pragma unroll
    for (int j = 0; j < 12; j++) {
        unsigned u = __float_as_uint(vals[j]);
        if (u > pref) cgt++;
        else if (u == pref) ceq++;
    }
    int inc = cgt;
#pragma unroll
    for (int off = 1; off < 32; off <<= 1) {
        int n_ = __shfl_up_sync(0xffffffffu, inc, off);
        if (lane >= off) inc += n_;
    }
    if (lane == 31) wsum[w] = inc;
    __syncthreads();
    if (w == 0) {
        int t = wsum[lane];
#pragma unroll
        for (int off = 1; off < 32; off <<= 1) {
            int n_ = __shfl_up_sync(0xffffffffu, t, off);
            if (lane >= off) t += n_;
        }
        wsum[lane] = t;
    }
    __syncthreads();
    int basep = (w > 0 ? wsum[w - 1] : 0) + inc - cgt;
    if (tid == 1023) total_s = basep + cgt;
    __syncthreads();
    const int total_gt = total_s;
    {
        int pos = basep;
#pragma unroll
        for (int j = 0; j < 12; j++)
            if (__float_as_uint(vals[j]) > pref) g_inds[b * KSEL + (pos++)] = f0 + j;
    }
    __syncthreads();
    inc = ceq;
#pragma unroll
    for (int off = 1; off < 32; off <<= 1) {
        int n_ = __shfl_up_sync(0xffffffffu, inc, off);
        if (lane >= off) inc += n_;
    }
    if (lane == 31) wsum[w] = inc;
    __syncthreads();
    if (w == 0) {
        int t = wsum[lane];
#pragma unroll
        for (int off = 1; off < 32; off <<= 1) {
            int n_ = __shfl_up_sync(0xffffffffu, t, off);
            if (lane >= off) t += n_;
        }
        wsum[lane] = t;
    }
    __syncthreads();
    int ebase = (w > 0 ? wsum[w - 1] : 0) + inc - ceq;
    const int need = KSEL - total_gt;
#pragma unroll
    for (int j = 0; j < 12; j++)
        if (__float_as_uint(vals[j]) == pref) {
            if (ebase < need) g_inds[b * KSEL + total_gt + ebase] = f0 + j;
            ebase++;
        }
}

// ---------------- kernel 4: gathered fc1 GEMM + gelu + delta ----------------
// grid (12, 32): blockIdx.x = ch-chunk, blockIdx.y = blk
__global__ __launch_bounds__(256) void k_gemm1(const float* __restrict__ x,
                                               const float* __restrict__ fc1w,
                                               const float* __restrict__ fc1b,
                                               const float* __restrict__ sAT) {
    extern __shared__ char dsm[];
    char* base = (char*)((((uintptr_t)dsm) + 1023) & ~(uintptr_t)1023);
    __shared__ int ridx[128];
    __shared__ float bsh[128];
    const int tid = threadIdx.x, wid = tid >> 5, lane = tid & 31;
    const int blk = blockIdx.y, mchunk = blockIdx.x;

#if TC_OK
    // ---------------- tcgen05 path: D[tok(128 lanes)][ch(128 cols)] ----------------
    __shared__ uint32_t s_tmem;
    __shared__ uint64_t s_mbar[2];
    const uint32_t sb = sm32(base);

    if (wid == 0) tc_alloc(sm32(&s_tmem), 128);
    if (tid == 0) { mbar_init(sm32(&s_mbar[0]), 1); mbar_init(sm32(&s_mbar[1]), 1); }
    if (tid < 128) {
        int id = g_inds[blk * KSEL + mchunk * 128 + tid];
        ridx[tid] = id;
        bsh[tid] = fc1b[id];
    }
    __syncthreads();
    const uint32_t tmem = s_tmem;
    const uint32_t mb0 = sm32(&s_mbar[0]), mb1 = sm32(&s_mbar[1]);

    const float* xb = x + (size_t)blk * BM_ * C_DIM;
    const int row = tid >> 3, c4 = tid & 7;
    float4 ra[4], rb[4];
#pragma unroll
    for (int r = 0; r < 4; r++) {
        int rr = row + 32 * r;
        ra[r] = *(const float4*)(xb + (size_t)rr * C_DIM + c4 * 4);
        rb[r] = *(const float4*)(fc1w + (size_t)ridx[rr] * C_DIM + c4 * 4);
    }
    const int NCH = C_DIM / 32;
    for (int i = 0; i < NCH; i++) {
        const int s = i & 1;
        if (i >= 2) mbar_wait(s ? mb1 : mb0, ((i >> 1) - 1) & 1);
        const uint32_t At = sb + (s * 2 + 0) * 16384, Bt = sb + (s * 2 + 1) * 16384;
#pragma unroll
        for (int r = 0; r < 4; r++) {
            int rr = row + 32 * r;
            uint32_t off = SWZ(rr * 128 + c4 * 16);
            *(uint4*)(base + (At - sb) + off) =
                make_uint4(f2tf(ra[r].x), f2tf(ra[r].y), f2tf(ra[r].z), f2tf(ra[r].w));
            *(uint4*)(base + (Bt - sb) + off) =
                make_uint4(f2tf(rb[r].x), f2tf(rb[r].y), f2tf(rb[r].z), f2tf(rb[r].w));
        }
        fence_async();
        if (i + 1 < NCH) {
            int k0 = (i + 1) * 32;
#pragma unroll
            for (int r = 0; r < 4; r++) {
                int rr = row + 32 * r;
                ra[r] = *(const float4*)(xb + (size_t)rr * C_DIM + k0 + c4 * 4);
                rb[r] = *(const float4*)(fc1w + (size_t)ridx[rr] * C_DIM + k0 + c4 * 4);
            }
        }
        __syncthreads();
        if (tid == 0) {
            uint64_t da = mk_desc(At), db = mk_desc(Bt);
#pragma unroll
            for (int ks = 0; ks < 4; ks++)
                mma_ss(tmem, da + ks * 2, db + ks * 2, (i | ks) ? 1u : 0u);
            tc_commit(s ? mb1 : mb0);
        }
    }
    mbar_wait(mb1, 1);
    tc_fence_after();
    const int subp = wid & 3, tok = subp * 32 + lane;
    const int cb = (wid >> 2) * 64;
#pragma unroll
    for (int g = 0; g < 2; g++) {
        uint32_t d[32];
        TC_LD32(d, tmem + cb + g * 32);
        tc_wait_ld();
        float o[32];
#pragma unroll
        for (int j = 0; j < 32; j++) {
            int chl = cb + g * 32 + j;
            float vm = __uint_as_float(d[j]) + bsh[chl];
            float cached = sAT[(size_t)ridx[chl] * NTOK + blk * BM_ + tok];
            o[j] = gelu_t(vm) - cached;
        }
        // tc path stores delta as [blk][tok][ch]
        float* dp = g_delta + ((size_t)blk * BM_ + tok) * KSEL + mchunk * 128 + cb + g * 32;
#pragma unroll
        for (int q = 0; q < 8; q++) *(float4*)(dp + q * 4) = *(float4*)&o[q * 4];
    }
    __syncthreads();
    if (wid == 0) { tc_relinq(); tc_dealloc(tmem, 128); }

#else
    // ---------------- fallback: mma.sync, C[ch][tok], delta stored [blk][ch][tok] --------
    const int G1_ST = 36;
    uint32_t* As = (uint32_t*)base;
    uint32_t* Bs = As + 128 * G1_ST;
    const int wm = wid & 1, wn = wid >> 1;
    const int grp = lane >> 2, tig = lane & 3;

    if (tid < 128) {
        int id = g_inds[blk * KSEL + mchunk * 128 + tid];
        ridx[tid] = id;
        bsh[tid] = fc1b[id];
    }
    __syncthreads();
    float acc[4][4][4];
#pragma unroll
    for (int i = 0; i < 4; i++)
#pragma unroll
        for (int j = 0; j < 4; j++)
#pragma unroll
            for (int q = 0; q < 4; q++) acc[i][j][q] = 0.f;

    const float* xb = x + (size_t)blk * BM_ * C_DIM;
    const int lrow = tid >> 3, lc4 = tid & 7;
    float4 ra[4], rb[4];
#pragma unroll
    for (int r = 0; r < 4; r++) {
        int rrow = lrow + 32 * r;
        ra[r] = *(const float4*)(fc1w + (size_t)ridx[rrow] * C_DIM + lc4 * 4);
        rb[r] = *(const float4*)(xb + (size_t)rrow * C_DIM + lc4 * 4);
    }
    for (int k0 = 0; k0 < C_DIM; k0 += 32) {
#pragma unroll
        for (int r = 0; r < 4; r++) {
            int rrow = lrow + 32 * r;
            int bidx = rrow * G1_ST + lc4 * 4;
            As[bidx + 0] = f2tf(ra[r].x); As[bidx + 1] = f2tf(ra[r].y);
            As[bidx + 2] = f2tf(ra[r].z); As[bidx + 3] = f2tf(ra[r].w);
            Bs[bidx + 0] = f2tf(rb[r].x); Bs[bidx + 1] = f2tf(rb[r].y);
            Bs[bidx + 2] = f2tf(rb[r].z); Bs[bidx + 3] = f2tf(rb[r].w);
        }
        __syncthreads();
        if (k0 + 32 < C_DIM) {
#pragma unroll
            for (int r = 0; r < 4; r++) {
                int rrow = lrow + 32 * r;
                ra[r] = *(const float4*)(fc1w + (size_t)ridx[rrow] * C_DIM + k0 + 32 + lc4 * 4);
                rb[r] = *(const float4*)(xb + (size_t)rrow * C_DIM + k0 + 32 + lc4 * 4);
            }
        }
#pragma unroll
        for (int ks = 0; ks < 4; ks++) {
            const int kk = ks * 8;
            uint32_t af[4][4], bf[4][2];
#pragma unroll
            for (int mt = 0; mt < 4; mt++) {
                int mr = wm * 64 + mt * 16 + grp;
                af[mt][0] = As[mr * G1_ST + kk + tig];
                af[mt][1] = As[(mr + 8) * G1_ST + kk + tig];
                af[mt][2] = As[mr * G1_ST + kk + tig + 4];
                af[mt][3] = As[(mr + 8) * G1_ST + kk + tig + 4];
            }
#pragma unroll
            for (int nt = 0; nt < 4; nt++) {
                int nb = wn * 32 + nt * 8 + grp;
                bf[nt][0] = Bs[nb * G1_ST + kk + tig];
                bf[nt][1] = Bs[nb * G1_ST + kk + tig + 4];
            }
#pragma unroll
            for (int mt = 0; mt < 4; mt++)
#pragma unroll
                for (int nt = 0; nt < 4; nt++) mma_frag(acc[mt][nt], af[mt], bf[nt]);
        }
        __syncthreads();
    }
#pragma unroll
    for (int mt = 0; mt < 4; mt++)
#pragma unroll
        for (int nt = 0; nt < 4; nt++) {
            int t0 = wn * 32 + nt * 8 + tig * 2;
#pragma unroll
            for (int half = 0; half < 2; half++) {
                int r = wm * 64 + mt * 16 + grp + 8 * half;
                float bb = bsh[r];
                int chg = ridx[r];
                const float* cp = sAT + (size_t)chg * NTOK + blk * BM_ + t0;
                float2 cached = *(const float2*)cp;
                float v0 = acc[mt][nt][half * 2 + 0] + bb;
                float v1 = acc[mt][nt][half * 2 + 1] + bb;
                float2 o;
                o.x = gelu_t(v0) - cached.x;
                o.y = gelu_t(v1) - cached.y;
                *(float2*)(g_delta + ((size_t)blk * KSEL + mchunk * 128 + r) * BM_ + t0) = o;
            }
        }
#endif
}

// ---------------- kernel 5: gathered fc2 GEMM + out_cache add ----------------
// grid (24, 32): blockIdx.x = c-tile, blockIdx.y = blk
__global__ __launch_bounds__(256) void k_gemm2(const float* __restrict__ fc2wT,
                                               const float* __restrict__ out_cache,
                                               float* __restrict__ out) {
    extern __shared__ char dsm[];
    char* base = (char*)((((uintptr_t)dsm) + 1023) & ~(uintptr_t)1023);
    __shared__ int kid[KSEL];
    const int tid = threadIdx.x, wid = tid >> 5, lane = tid & 31;
    const int blk = blockIdx.y, n0 = blockIdx.x * 128;

#if TC_OK
    // ---------------- tcgen05 path: D[tok][c]; A=delta [blk][tok][ch] K-major ------------
    __shared__ uint32_t s_tmem;
    __shared__ uint64_t s_mbar[2];
    const uint32_t sb = sm32(base);

    if (wid == 0) tc_alloc(sm32(&s_tmem), 128);
    if (tid == 0) { mbar_init(sm32(&s_mbar[0]), 1); mbar_init(sm32(&s_mbar[1]), 1); }
    for (int i = tid; i < KSEL; i += 256) kid[i] = g_inds[blk * KSEL + i];
    __syncthreads();
    const uint32_t tmem = s_tmem;
    const uint32_t mb0 = sm32(&s_mbar[0]), mb1 = sm32(&s_mbar[1]);

    const float* Ab = g_delta + (size_t)blk * BM_ * KSEL;
    const int row = tid >> 3, c4 = tid & 7;
    float4 ra[4];
    float rbv[4][4];
#pragma unroll
    for (int r = 0; r < 4; r++)
        ra[r] = *(const float4*)(Ab + (size_t)(row + 32 * r) * KSEL + c4 * 4);
#pragma unroll
    for (int j = 0; j < 4; j++) {
        int idx = tid + 256 * j;
        int c = idx & 127, ch4 = idx >> 7;
#pragma unroll
        for (int q = 0; q < 4; q++)
            rbv[j][q] = fc2wT[(size_t)kid[ch4 * 4 + q] * C_DIM + n0 + c];
    }
    const int NCH = KSEL / 32;  // 48
    for (int i = 0; i < NCH; i++) {
        const int s = i & 1;
        if (i >= 2) mbar_wait(s ? mb1 : mb0, ((i >> 1) - 1) & 1);
        const uint32_t At = sb + (s * 2 + 0) * 16384, Bt = sb + (s * 2 + 1) * 16384;
#pragma unroll
        for (int r = 0; r < 4; r++) {
            int rr = row + 32 * r;
            uint32_t off = SWZ(rr * 128 + c4 * 16);
            *(uint4*)(base + (At - sb) + off) =
                make_uint4(f2tf(ra[r].x), f2tf(ra[r].y), f2tf(ra[r].z), f2tf(ra[r].w));
        }
#pragma unroll
        for (int j = 0; j < 4; j++) {
            int idx = tid + 256 * j;
            int c = idx & 127, ch4 = idx >> 7;
            uint32_t off = SWZ(c * 128 + ch4 * 16);
            *(uint4*)(base + (Bt - sb) + off) =
                make_uint4(f2tf(rbv[j][0]), f2tf(rbv[j][1]), f2tf(rbv[j][2]), f2tf(rbv[j][3]));
        }
        fence_async();
        if (i + 1 < NCH) {
            int k0 = (i + 1) * 32;
#pragma unroll
            for (int r = 0; r < 4; r++)
                ra[r] = *(const float4*)(Ab + (size_t)(row + 32 * r) * KSEL + k0 + c4 * 4);
#pragma unroll
            for (int j = 0; j < 4; j++) {
                int idx = tid + 256 * j;
                int c = idx & 127, ch4 = idx >> 7;
#pragma unroll
                for (int q = 0; q < 4; q++)
                    rbv[j][q] = fc2wT[(size_t)kid[k0 + ch4 * 4 + q] * C_DIM + n0 + c];
            }
        }
        __syncthreads();
        if (tid == 0) {
            uint64_t da = mk_desc(At), db = mk_desc(Bt);
#pragma unroll
            for (int ks = 0; ks < 4; ks++)
                mma_ss(tmem, da + ks * 2, db + ks * 2, (i | ks) ? 1u : 0u);
            tc_commit(s ? mb1 : mb0);
        }
    }
    mbar_wait(mb1, 1);
    tc_fence_after();
    const int subp = wid & 3, tok = subp * 32 + lane;
    const int cb = (wid >> 2) * 64;
#pragma unroll
    for (int g = 0; g < 2; g++) {
        uint32_t d[32];
        TC_LD32(d, tmem + cb + g * 32);
        tc_wait_ld();
        size_t off = (size_t)(blk * BM_ + tok) * C_DIM + n0 + cb + g * 32;
#pragma unroll
        for (int q = 0; q < 8; q++) {
            float4 oc = *(const float4*)(out_cache + off + q * 4);
            oc.x += __uint_as_float(d[q * 4 + 0]);
            oc.y += __uint_as_float(d[q * 4 + 1]);
            oc.z += __uint_as_float(d[q * 4 + 2]);
            oc.w += __uint_as_float(d[q * 4 + 3]);
            *(float4*)(out + off + q * 4) = oc;
        }
    }
    __syncthreads();
    if (wid == 0) { tc_relinq(); tc_dealloc(tmem, 128); }

#else
    // ---------------- fallback: mma.sync; A=delta [blk][ch][tok] ----------------
    const int G2_ST = 136;
    uint32_t* As = (uint32_t*)base;
    uint32_t* Bs = As + 32 * G2_ST;
    const int wm = wid & 1, wn = wid >> 1;
    const int grp = lane >> 2, tig = lane & 3;

    for (int i = tid; i < KSEL; i += 256) kid[i] = g_inds[blk * KSEL + i];
    __syncthreads();

    float acc[4][4][4];
#pragma unroll
    for (int i = 0; i < 4; i++)
#pragma unroll
        for (int j = 0; j < 4; j++)
#pragma unroll
            for (int q = 0; q < 4; q++) acc[i][j][q] = 0.f;

    const float* Ab = g_delta + (size_t)blk * KSEL * BM_;
    float4 ra[4], rb[4];
#pragma unroll
    for (int r = 0; r < 4; r++) {
        int idx = tid + 256 * r;
        int ch = idx >> 5, t4 = idx & 31;
        ra[r] = *(const float4*)(Ab + (size_t)ch * BM_ + t4 * 4);
        rb[r] = *(const float4*)(fc2wT + (size_t)kid[ch] * C_DIM + n0 + t4 * 4);
    }
    for (int k0 = 0; k0 < KSEL; k0 += 32) {
#pragma unroll
        for (int r = 0; r < 4; r++) {
            int idx = tid + 256 * r;
            int ch = idx >> 5, t4 = idx & 31;
            int bidx = ch * G2_ST + t4 * 4;
            As[bidx + 0] = f2tf(ra[r].x); As[bidx + 1] = f2tf(ra[r].y);
            As[bidx + 2] = f2tf(ra[r].z); As[bidx + 3] = f2tf(ra[r].w);
            Bs[bidx + 0] = f2tf(rb[r].x); Bs[bidx + 1] = f2tf(rb[r].y);
            Bs[bidx + 2] = f2tf(rb[r].z); Bs[bidx + 3] = f2tf(rb[r].w);
        }
        __syncthreads();
        if (k0 + 32 < KSEL) {
#pragma unroll
            for (int r = 0; r < 4; r++) {
                int idx = tid + 256 * r;
                int ch = idx >> 5, t4 = idx & 31;
                ra[r] = *(const float4*)(Ab + (size_t)(k0 + 32 + ch) * BM_ + t4 * 4);
                rb[r] = *(const float4*)(fc2wT + (size_t)kid[k0 + 32 + ch] * C_DIM + n0 + t4 * 4);
            }
        }
#pragma unroll
        for (int ks = 0; ks < 4; ks++) {
            const int kk = ks * 8;
            uint32_t af[4][4], bf[4][2];
#pragma unroll
            for (int mt = 0; mt < 4; mt++) {
                int mbr = wm * 64 + mt * 16 + grp;
                af[mt][0] = As[(kk + tig) * G2_ST + mbr];
                af[mt][1] = As[(kk + tig) * G2_ST + mbr + 8];
                af[mt][2] = As[(kk + tig + 4) * G2_ST + mbr];
                af[mt][3] = As[(kk + tig + 4) * G2_ST + mbr + 8];
            }
#pragma unroll
            for (int nt = 0; nt < 4; nt++) {
                int nb = wn * 32 + nt * 8 + grp;
                bf[nt][0] = Bs[(kk + tig) * G2_ST + nb];
                bf[nt][1] = Bs[(kk + tig + 4) * G2_ST + nb];
            }
#pragma unroll
            for (int mt = 0; mt < 4; mt++)
#pragma unroll
                for (int nt = 0; nt < 4; nt++) mma_frag(acc[mt][nt], af[mt], bf[nt]);
        }
        __syncthreads();
    }
#pragma unroll
    for (int mt = 0; mt < 4; mt++)
#pragma unroll
        for (int nt = 0; nt < 4; nt++) {
            int col = n0 + wn * 32 + nt * 8 + tig * 2;
#pragma unroll
            for (int half = 0; half < 2; half++) {
                int trow = wm * 64 + mt * 16 + grp + 8 * half;
                size_t off = (size_t)(blk * BM_ + trow) * C_DIM + col;
                float2 oc = *(const float2*)(out_cache + off);
                float2 o;
                o.x = oc.x + acc[mt][nt][half * 2 + 0];
                o.y = oc.y + acc[mt][nt][half * 2 + 1];
                *(float2*)(out + off) = o;
            }
        }
#endif
}

// ---------------- launch ----------------
extern "C" void kernel_launch(void* const* d_in, const int* in_sizes, int n_in,
                              void* d_out, int out_size) {
    const float* x     = (const float*)d_in[0];
    const float* fc1w  = (const float*)d_in[1];
    const float* fc1b  = (const float*)d_in[2];
    const float* fc2wT = (const float*)d_in[3];
    const float* bmc   = (const float*)d_in[4];
    const float* sAT   = (const float*)d_in[5];
    const float* outc  = (const float*)d_in[6];
    float* out = (float*)d_out;

    static int attr_done = 0;
    if (!attr_done) {
        cudaFuncSetAttribute(k_sel,   cudaFuncAttributeMaxDynamicSharedMemorySize, SEL_SMEM);
        cudaFuncSetAttribute(k_gemm1, cudaFuncAttributeMaxDynamicSharedMemorySize, G_SMEM);
        cudaFuncSetAttribute(k_gemm2, cudaFuncAttributeMaxDynamicSharedMemorySize, G_SMEM);
        attr_done = 1;
    }

    k_bmean<<<dim3(256, 6), 512>>>(x);
    k_sel<<<dim3(96, 2), 256, SEL_SMEM>>>(fc1w, fc1b, bmc);
    k_topk<<<32, 1024>>>();
    k_gemm1<<<dim3(12, 32), 256, G_SMEM>>>(x, fc1w, fc1b, sAT);
    k_gemm2<<<dim3(24, 32), 256, G_SMEM>>>(fc2wT, outc, out);
}

// round 6
// speedup vs baseline: 1.8084x; 1.2409x over previous
#include <cuda_runtime.h>
#include <cstdint>

#if defined(__CUDA_ARCH_FEAT_SM103_ALL) || defined(__CUDA_ARCH_FEAT_SM100_ALL) || \
    (defined(__CUDA_ARCH_FAMILY_SPECIFIC__) && (__CUDA_ARCH_FAMILY_SPECIFIC__ >= 1000))
#define TC_OK 1
#else
#define TC_OK 0
#endif

#define NTOK 4096
#define C_DIM 3072
#define F_DIM 12288
#define NB 32
#define BM_ 128
#define MBM_ 16
#define MBS 256
#define KSEL 1536

// idesc: dtype F32(1<<4), atype TF32(2<<7), btype TF32(2<<10), N=128(16<<17), M=128(8<<24)
#define IDESC_TF32 ((1u<<4)|(2u<<7)|(2u<<10)|(16u<<17)|(8u<<24))
#define SWZ(o) ((o) ^ (((o) >> 3) & 0x70))

#define SEL_SMEM (8 * 16384 + 1024)
#define G_SMEM   (4 * 16384 + 1024)

// ---------------- scratch ----------------
__device__ float g_bmx[MBS * C_DIM];
__device__ float g_mdiff[NB * F_DIM];
__device__ int   g_inds[NB * KSEL];
__device__ float g_delta[(size_t)NB * BM_ * KSEL];

// ---------------- common helpers ----------------
__device__ __forceinline__ uint32_t f2tf(float x) {
    uint32_t u; asm("cvt.rna.tf32.f32 %0, %1;" : "=r"(u) : "f"(x)); return u;
}
__device__ __forceinline__ float gelu_t(float v) {
    return 0.5f * v * (1.f + tanhf(0.7978845608028654f * (v + 0.044715f * v * v * v)));
}
// legacy mma.sync (fallback path)
__device__ __forceinline__ void mma_frag(float c[4], const uint32_t a[4], const uint32_t b[2]) {
    asm volatile(
        "mma.sync.aligned.m16n8k8.row.col.f32.tf32.tf32.f32 "
        "{%0,%1,%2,%3},{%4,%5,%6,%7},{%8,%9},{%0,%1,%2,%3};"
        : "+f"(c[0]), "+f"(c[1]), "+f"(c[2]), "+f"(c[3])
        : "r"(a[0]), "r"(a[1]), "r"(a[2]), "r"(a[3]), "r"(b[0]), "r"(b[1]));
}

#if TC_OK
// ---------------- tcgen05 helpers ----------------
__device__ __forceinline__ uint32_t sm32(const void* p) {
    uint32_t a;
    asm("{ .reg .u64 t; cvta.to.shared.u64 t, %1; cvt.u32.u64 %0, t; }" : "=r"(a) : "l"(p));
    return a;
}
__device__ __forceinline__ void mbar_init(uint32_t m, uint32_t c) {
    asm volatile("mbarrier.init.shared.b64 [%0], %1;" :: "r"(m), "r"(c) : "memory");
}
__device__ __forceinline__ void mbar_wait(uint32_t m, uint32_t par) {
    asm volatile(
        "{\n\t.reg .pred P;\n"
        "W_%=:\n\t"
        "mbarrier.try_wait.parity.acquire.cta.shared::cta.b64 P, [%0], %1, 0x989680;\n\t"
        "@!P bra.uni W_%=;\n\t}"
        :: "r"(m), "r"(par) : "memory");
}
__device__ __forceinline__ void tc_alloc(uint32_t slot, uint32_t n) {
    asm volatile("tcgen05.alloc.cta_group::1.sync.aligned.shared::cta.b32 [%0], %1;"
                 :: "r"(slot), "r"(n) : "memory");
}
__device__ __forceinline__ void tc_relinq() {
    asm volatile("tcgen05.relinquish_alloc_permit.cta_group::1.sync.aligned;");
}
__device__ __forceinline__ void tc_dealloc(uint32_t t, uint32_t n) {
    asm volatile("tcgen05.dealloc.cta_group::1.sync.aligned.b32 %0, %1;" :: "r"(t), "r"(n));
}
__device__ __forceinline__ void tc_commit(uint32_t m) {
    asm volatile("tcgen05.commit.cta_group::1.mbarrier::arrive::one.shared::cluster.b64 [%0];"
                 :: "r"(m) : "memory");
}
__device__ __forceinline__ void fence_async() {
    asm volatile("fence.proxy.async.shared::cta;" ::: "memory");
}
__device__ __forceinline__ void tc_fence_after() {
    asm volatile("tcgen05.fence::after_thread_sync;" ::: "memory");
}
__device__ __forceinline__ void tc_wait_ld() {
    asm volatile("tcgen05.wait::ld.sync.aligned;" ::: "memory");
}
__device__ __forceinline__ void mma_ss(uint32_t d, uint64_t a, uint64_t b, uint32_t en) {
    asm volatile(
        "{\n\t.reg .pred p;\n\t"
        "setp.ne.u32 p, %5, 0;\n\t"
        "tcgen05.mma.cta_group::1.kind::tf32 [%0], %1, %2, %3, {%4,%4,%4,%4}, p;\n\t}"
        :: "r"(d), "l"(a), "l"(b), "r"(IDESC_TF32), "r"(0u), "r"(en) : "memory");
}
__device__ __forceinline__ uint64_t mk_desc(uint32_t addr) {
    const uint64_t base = (uint64_t(2) << 61) | (uint64_t(1) << 46) |
                          (uint64_t(64) << 32) | (uint64_t(1) << 16);
    return base | ((uint64_t)(addr >> 4) & 0x3FFF);
}
#define TC_LD32(r, a) \
    asm volatile( \
        "tcgen05.ld.sync.aligned.32x32b.x32.b32 " \
        "{%0,%1,%2,%3,%4,%5,%6,%7,%8,%9,%10,%11,%12,%13,%14,%15," \
        "%16,%17,%18,%19,%20,%21,%22,%23,%24,%25,%26,%27,%28,%29,%30,%31}, [%32];" \
        : "=r"((r)[0]),"=r"((r)[1]),"=r"((r)[2]),"=r"((r)[3]),"=r"((r)[4]),"=r"((r)[5]), \
          "=r"((r)[6]),"=r"((r)[7]),"=r"((r)[8]),"=r"((r)[9]),"=r"((r)[10]),"=r"((r)[11]), \
          "=r"((r)[12]),"=r"((r)[13]),"=r"((r)[14]),"=r"((r)[15]),"=r"((r)[16]),"=r"((r)[17]), \
          "=r"((r)[18]),"=r"((r)[19]),"=r"((r)[20]),"=r"((r)[21]),"=r"((r)[22]),"=r"((r)[23]), \
          "=r"((r)[24]),"=r"((r)[25]),"=r"((r)[26]),"=r"((r)[27]),"=r"((r)[28]),"=r"((r)[29]), \
          "=r"((r)[30]),"=r"((r)[31]) : "r"(a))
#endif  // TC_OK

// ---------------- kernel 1: block means ----------------
__global__ void k_bmean(const float* __restrict__ x) {
    int mb = blockIdx.x;
    int c  = blockIdx.y * 512 + threadIdx.x;
    const float* p = x + (size_t)mb * MBM_ * C_DIM + c;
    float s = 0.f;
#pragma unroll
    for (int t = 0; t < MBM_; t++) s += p[(size_t)t * C_DIM];
    g_bmx[mb * C_DIM + c] = s * (1.f / 16.f);
}

// ---------------- kernel 2: selection GEMM (3xTF32) fused bias+|diff|+rsum --------------
__global__ __launch_bounds__(256) void k_sel(const float* __restrict__ fc1w,
                                             const float* __restrict__ fc1b,
                                             const float* __restrict__ bmc) {
    extern __shared__ char dsm[];
    char* base = (char*)((((uintptr_t)dsm) + 1023) & ~(uintptr_t)1023);
    const int tid = threadIdx.x, wid = tid >> 5, lane = tid & 31;

#if TC_OK
    __shared__ uint32_t s_tmem;
    __shared__ uint64_t s_mbar[2];
    const int m0 = blockIdx.x * 128, n0 = blockIdx.y * 128;
    const uint32_t sb = sm32(base);

    if (wid == 0) { tc_alloc(sm32(&s_tmem), 128); tc_relinq(); }
    if (tid == 0) { mbar_init(sm32(&s_mbar[0]), 1); mbar_init(sm32(&s_mbar[1]), 1); }
    __syncthreads();
    const uint32_t tmem = s_tmem;
    const uint32_t mb0 = sm32(&s_mbar[0]), mb1 = sm32(&s_mbar[1]);

    const int row = tid >> 3, c4 = tid & 7;
    float4 ra[4], rb[4];
#pragma unroll
    for (int r = 0; r < 4; r++) {
        int rr = row + 32 * r;
        ra[r] = *(const float4*)(fc1w + (size_t)(m0 + rr) * C_DIM + c4 * 4);
        rb[r] = *(const float4*)(g_bmx + (size_t)(n0 + rr) * C_DIM + c4 * 4);
    }
    const int NCH = C_DIM / 32;  // 96
    for (int i = 0; i < NCH; i++) {
        const int s = i & 1;
        if (i >= 2) mbar_wait(s ? mb1 : mb0, ((i >> 1) - 1) & 1);
        const uint32_t Ah = sb + (s * 4 + 0) * 16384, Al = sb + (s * 4 + 1) * 16384;
        const uint32_t Bh = sb + (s * 4 + 2) * 16384, Bl = sb + (s * 4 + 3) * 16384;
#pragma unroll
        for (int r = 0; r < 4; r++) {
            int rr = row + 32 * r;
            uint32_t off = SWZ(rr * 128 + c4 * 16);
            float av[4] = {ra[r].x, ra[r].y, ra[r].z, ra[r].w};
            float bv[4] = {rb[r].x, rb[r].y, rb[r].z, rb[r].w};
            uint4 h, l;
            h.x = f2tf(av[0]); l.x = f2tf(av[0] - __uint_as_float(h.x));
            h.y = f2tf(av[1]); l.y = f2tf(av[1] - __uint_as_float(h.y));
            h.z = f2tf(av[2]); l.z = f2tf(av[2] - __uint_as_float(h.z));
            h.w = f2tf(av[3]); l.w = f2tf(av[3] - __uint_as_float(h.w));
            *(uint4*)(base + (Ah - sb) + off) = h;
            *(uint4*)(base + (Al - sb) + off) = l;
            h.x = f2tf(bv[0]); l.x = f2tf(bv[0] - __uint_as_float(h.x));
            h.y = f2tf(bv[1]); l.y = f2tf(bv[1] - __uint_as_float(h.y));
            h.z = f2tf(bv[2]); l.z = f2tf(bv[2] - __uint_as_float(h.z));
            h.w = f2tf(bv[3]); l.w = f2tf(bv[3] - __uint_as_float(h.w));
            *(uint4*)(base + (Bh - sb) + off) = h;
            *(uint4*)(base + (Bl - sb) + off) = l;
        }
        fence_async();
        if (i + 1 < NCH) {
            int k0 = (i + 1) * 32;
#pragma unroll
            for (int r = 0; r < 4; r++) {
                int rr = row + 32 * r;
                ra[r] = *(const float4*)(fc1w + (size_t)(m0 + rr) * C_DIM + k0 + c4 * 4);
                rb[r] = *(const float4*)(g_bmx + (size_t)(n0 + rr) * C_DIM + k0 + c4 * 4);
            }
        }
        __syncthreads();
        if (tid == 0) {
            uint64_t dah = mk_desc(Ah), dal = mk_desc(Al);
            uint64_t dbh = mk_desc(Bh), dbl = mk_desc(Bl);
#pragma unroll
            for (int ks = 0; ks < 4; ks++) {
                mma_ss(tmem, dah + ks * 2, dbl + ks * 2, (i | ks) ? 1u : 0u);
                mma_ss(tmem, dal + ks * 2, dbh + ks * 2, 1u);
                mma_ss(tmem, dah + ks * 2, dbh + ks * 2, 1u);
            }
            tc_commit(s ? mb1 : mb0);
        }
    }
    mbar_wait(mb1, 1);  // chunk 95 -> buffer 1, idx 47 -> parity 1
    tc_fence_after();
    const int subp = wid & 3, l = subp * 32 + lane;
    const int f = m0 + l;
    const float bias = fc1b[f];
    const int cb = (wid >> 2) * 64;
    float sum[8];
#pragma unroll
    for (int q = 0; q < 8; q++) sum[q] = 0.f;
#pragma unroll
    for (int g = 0; g < 2; g++) {
        uint32_t d[32];
        TC_LD32(d, tmem + cb + g * 32);
        tc_wait_ld();
#pragma unroll
        for (int j = 0; j < 32; j++) {
            int mbi = n0 + cb + g * 32 + j;
            float val = __uint_as_float(d[j]) + bias;
            sum[(g * 32 + j) >> 3] += fabsf(val - bmc[(size_t)mbi * F_DIM + f]);
        }
    }
    const int b0 = (n0 + cb) >> 3;
#pragma unroll
    for (int q = 0; q < 8; q++) g_mdiff[(size_t)(b0 + q) * F_DIM + f] = sum[q];
    __syncthreads();
    if (wid == 0) tc_dealloc(tmem, 128);

#else
    // fallback: mma.sync 3xTF32, C[mb][f], fused mdiff epilogue
    const int SEL_ST = 20;
    uint32_t* Ah = (uint32_t*)base;
    uint32_t* Al = Ah + 128 * SEL_ST;
    uint32_t* Bh = Al + 128 * SEL_ST;
    uint32_t* Bl = Bh + 128 * SEL_ST;
    float* S = (float*)(Bl + 128 * SEL_ST);
    const int m0 = blockIdx.y * 128, n0 = blockIdx.x * 128;
    const int wm = wid & 1, wn = wid >> 1;
    const int grp = lane >> 2, tig = lane & 3;

    float acc[4][4][4];
#pragma unroll
    for (int i = 0; i < 4; i++)
#pragma unroll
        for (int j = 0; j < 4; j++)
#pragma unroll
            for (int q = 0; q < 4; q++) acc[i][j][q] = 0.f;

    float4 ra[2], rb[2];
    const int lrow = tid >> 2, lc4 = tid & 3;
#pragma unroll
    for (int r = 0; r < 2; r++) {
        int rrow = lrow + 64 * r;
        ra[r] = *(const float4*)(g_bmx + (size_t)(m0 + rrow) * C_DIM + lc4 * 4);
        rb[r] = *(const float4*)(fc1w + (size_t)(n0 + rrow) * C_DIM + lc4 * 4);
    }
    for (int k0 = 0; k0 < C_DIM; k0 += 16) {
#pragma unroll
        for (int r = 0; r < 2; r++) {
            int rrow = lrow + 64 * r;
            int bidx = rrow * SEL_ST + lc4 * 4;
            float av[4] = {ra[r].x, ra[r].y, ra[r].z, ra[r].w};
            float bv[4] = {rb[r].x, rb[r].y, rb[r].z, rb[r].w};
#pragma unroll
            for (int i = 0; i < 4; i++) {
                uint32_t h = f2tf(av[i]);
                Ah[bidx + i] = h;
                Al[bidx + i] = f2tf(av[i] - __uint_as_float(h));
                h = f2tf(bv[i]);
                Bh[bidx + i] = h;
                Bl[bidx + i] = f2tf(bv[i] - __uint_as_float(h));
            }
        }
        __syncthreads();
        if (k0 + 16 < C_DIM) {
#pragma unroll
            for (int r = 0; r < 2; r++) {
                int rrow = lrow + 64 * r;
                ra[r] = *(const float4*)(g_bmx + (size_t)(m0 + rrow) * C_DIM + k0 + 16 + lc4 * 4);
                rb[r] = *(const float4*)(fc1w + (size_t)(n0 + rrow) * C_DIM + k0 + 16 + lc4 * 4);
            }
        }
#pragma unroll
        for (int ks = 0; ks < 2; ks++) {
            const int kk = ks * 8;
            uint32_t ah[4][4], al[4][4], bh[4][2], bl[4][2];
#pragma unroll
            for (int mt = 0; mt < 4; mt++) {
                int mr = wm * 64 + mt * 16 + grp;
                ah[mt][0] = Ah[mr * SEL_ST + kk + tig];
                ah[mt][1] = Ah[(mr + 8) * SEL_ST + kk + tig];
                ah[mt][2] = Ah[mr * SEL_ST + kk + tig + 4];
                ah[mt][3] = Ah[(mr + 8) * SEL_ST + kk + tig + 4];
                al[mt][0] = Al[mr * SEL_ST + kk + tig];
                al[mt][1] = Al[(mr + 8) * SEL_ST + kk + tig];
                al[mt][2] = Al[mr * SEL_ST + kk + tig + 4];
                al[mt][3] = Al[(mr + 8) * SEL_ST + kk + tig + 4];
            }
#pragma unroll
            for (int nt = 0; nt < 4; nt++) {
                int nb = wn * 32 + nt * 8 + grp;
                bh[nt][0] = Bh[nb * SEL_ST + kk + tig];
                bh[nt][1] = Bh[nb * SEL_ST + kk + tig + 4];
                bl[nt][0] = Bl[nb * SEL_ST + kk + tig];
                bl[nt][1] = Bl[nb * SEL_ST + kk + tig + 4];
            }
#pragma unroll
            for (int mt = 0; mt < 4; mt++)
#pragma unroll
                for (int nt = 0; nt < 4; nt++) {
                    mma_frag(acc[mt][nt], ah[mt], bl[nt]);
                    mma_frag(acc[mt][nt], al[mt], bh[nt]);
                    mma_frag(acc[mt][nt], ah[mt], bh[nt]);
                }
        }
        __syncthreads();
    }
#pragma unroll
    for (int mt = 0; mt < 4; mt++)
#pragma unroll
        for (int nt = 0; nt < 4; nt++) {
            int m_l = wm * 64 + mt * 16 + grp;
            int n_l = wn * 32 + nt * 8 + tig * 2;
            S[n_l * 129 + m_l]           = acc[mt][nt][0];
            S[(n_l + 1) * 129 + m_l]     = acc[mt][nt][1];
            S[n_l * 129 + m_l + 8]       = acc[mt][nt][2];
            S[(n_l + 1) * 129 + m_l + 8] = acc[mt][nt][3];
        }
    __syncthreads();
    const int f_l = tid & 127, gh = tid >> 7;
    const int fg = n0 + f_l;
    const float bias = fc1b[fg];
#pragma unroll
    for (int q = 0; q < 8; q++) {
        int mb_l0 = (gh * 8 + q) * 8;
        float s = 0.f;
#pragma unroll
        for (int t = 0; t < 8; t++)
            s += fabsf(S[f_l * 129 + mb_l0 + t] + bias -
                       bmc[(size_t)(m0 + mb_l0 + t) * F_DIM + fg]);
        g_mdiff[(size_t)((m0 + mb_l0) >> 3) * F_DIM + fg] = s;
    }
#endif
}

// ---------------- kernel 3: parallel top-1536 (radix select) ----------------
__global__ __launch_bounds__(1024) void k_topk() {
    const int b = blockIdx.x, tid = threadIdx.x;
    const int lane = tid & 31, w = tid >> 5;
    const float* v = g_mdiff + (size_t)b * F_DIM;
    const int f0 = tid * 12;
    float vals[12];
#pragma unroll
    for (int j = 0; j < 12; j++) vals[j] = v[f0 + j];

    __shared__ int hist[256];
    __shared__ unsigned pref_s;
    __shared__ int rem_s;
    __shared__ int wsum[32];
    __shared__ int total_s;

    unsigned pref = 0;
    int rem = KSEL;
    for (int pass = 0; pass < 4; pass++) {
        const int sh = 24 - 8 * pass;
        if (tid < 256) hist[tid] = 0;
        __syncthreads();
#pragma unroll
        for (int j = 0; j < 12; j++) {
            unsigned u = __float_as_uint(vals[j]);
            if (pass == 0 || (u >> (sh + 8)) == pref)
                atomicAdd(&hist[(u >> sh) & 255], 1);
        }
        __syncthreads();
        for (int off = 1; off < 256; off <<= 1) {
            int x_;
            if (tid < 256) x_ = hist[tid] + ((tid + off < 256) ? hist[tid + off] : 0);
            __syncthreads();
            if (tid < 256) hist[tid] = x_;
            __syncthreads();
        }
        if (tid < 256) {
            int nxt = (tid == 255) ? 0 : hist[tid + 1];
            if (hist[tid] >= rem && nxt < rem) {
                pref_s = (pref << 8) | (unsigned)tid;
                rem_s = rem - nxt;
            }
        }
        __syncthreads();
        pref = pref_s;
        rem = rem_s;
        __syncthreads();
    }
    int cgt = 0, ceq = 0;
#pragma unroll
    for (int j = 0; j < 12; j++) {
        unsigned u = __float_as_uint(vals[j]);
        if (u > pref) cgt++;
        else if (u == pref) ceq++;
    }
    int inc = cgt;
#pragma unroll
    for (int off = 1; off < 32; off <<= 1) {
        int n_ = __shfl_up_sync(0xffffffffu, inc, off);
        if (lane >= off) inc += n_;
    }
    if (lane == 31) wsum[w] = inc;
    __syncthreads();
    if (w == 0) {
        int t = wsum[lane];
#pragma unroll
        for (int off = 1; off < 32; off <<= 1) {
            int n_ = __shfl_up_sync(0xffffffffu, t, off);
            if (lane >= off) t += n_;
        }
        wsum[lane] = t;
    }
    __syncthreads();
    int basep = (w > 0 ? wsum[w - 1] : 0) + inc - cgt;
    if (tid == 1023) total_s = basep + cgt;
    __syncthreads();
    const int total_gt = total_s;
    {
        int pos = basep;
#pragma unroll
        for (int j = 0; j < 12; j++)
            if (__float_as_uint(vals[j]) > pref) g_inds[b * KSEL + (pos++)] = f0 + j;
    }
    __syncthreads();
    inc = ceq;
#pragma unroll
    for (int off = 1; off < 32; off <<= 1) {
        int n_ = __shfl_up_sync(0xffffffffu, inc, off);
        if (lane >= off) inc += n_;
    }
    if (lane == 31) wsum[w] = inc;
    __syncthreads();
    if (w == 0) {
        int t = wsum[lane];
#pragma unroll
        for (int off = 1; off < 32; off <<= 1) {
            int n_ = __shfl_up_sync(0xffffffffu, t, off);
            if (lane >= off) t += n_;
        }
        wsum[lane] = t;
    }
    __syncthreads();
    int ebase = (w > 0 ? wsum[w - 1] : 0) + inc - ceq;
    const int need = KSEL - total_gt;
#pragma unroll
    for (int j = 0; j < 12; j++)
        if (__float_as_uint(vals[j]) == pref) {
            if (ebase < need) g_inds[b * KSEL + total_gt + ebase] = f0 + j;
            ebase++;
        }
}

// ---------------- kernel 4: gathered fc1 GEMM + gelu + delta ----------------
__global__ __launch_bounds__(256) void k_gemm1(const float* __restrict__ x,
                                               const float* __restrict__ fc1w,
                                               const float* __restrict__ fc1b,
                                               const float* __restrict__ sAT) {
    extern __shared__ char dsm[];
    char* base = (char*)((((uintptr_t)dsm) + 1023) & ~(uintptr_t)1023);
    __shared__ int ridx[128];
    __shared__ float bsh[128];
    const int tid = threadIdx.x, wid = tid >> 5, lane = tid & 31;
    const int blk = blockIdx.y, mchunk = blockIdx.x;

#if TC_OK
    __shared__ uint32_t s_tmem;
    __shared__ uint64_t s_mbar[2];
    const uint32_t sb = sm32(base);

    if (wid == 0) { tc_alloc(sm32(&s_tmem), 128); tc_relinq(); }
    if (tid == 0) { mbar_init(sm32(&s_mbar[0]), 1); mbar_init(sm32(&s_mbar[1]), 1); }
    if (tid < 128) {
        int id = g_inds[blk * KSEL + mchunk * 128 + tid];
        ridx[tid] = id;
        bsh[tid] = fc1b[id];
    }
    __syncthreads();
    const uint32_t tmem = s_tmem;
    const uint32_t mb0 = sm32(&s_mbar[0]), mb1 = sm32(&s_mbar[1]);

    const float* xb = x + (size_t)blk * BM_ * C_DIM;
    const int row = tid >> 3, c4 = tid & 7;
    float4 ra[4], rb[4];
#pragma unroll
    for (int r = 0; r < 4; r++) {
        int rr = row + 32 * r;
        ra[r] = *(const float4*)(xb + (size_t)rr * C_DIM + c4 * 4);
        rb[r] = *(const float4*)(fc1w + (size_t)ridx[rr] * C_DIM + c4 * 4);
    }
    const int NCH = C_DIM / 32;
    for (int i = 0; i < NCH; i++) {
        const int s = i & 1;
        if (i >= 2) mbar_wait(s ? mb1 : mb0, ((i >> 1) - 1) & 1);
        const uint32_t At = sb + (s * 2 + 0) * 16384, Bt = sb + (s * 2 + 1) * 16384;
#pragma unroll
        for (int r = 0; r < 4; r++) {
            int rr = row + 32 * r;
            uint32_t off = SWZ(rr * 128 + c4 * 16);
            *(float4*)(base + (At - sb) + off) = ra[r];   // raw fp32; tf32 HW truncation
            *(float4*)(base + (Bt - sb) + off) = rb[r];
        }
        fence_async();
        if (i + 1 < NCH) {
            int k0 = (i + 1) * 32;
#pragma unroll
            for (int r = 0; r < 4; r++) {
                int rr = row + 32 * r;
                ra[r] = *(const float4*)(xb + (size_t)rr * C_DIM + k0 + c4 * 4);
                rb[r] = *(const float4*)(fc1w + (size_t)ridx[rr] * C_DIM + k0 + c4 * 4);
            }
        }
        __syncthreads();
        if (tid == 0) {
            uint64_t da = mk_desc(At), db = mk_desc(Bt);
#pragma unroll
            for (int ks = 0; ks < 4; ks++)
                mma_ss(tmem, da + ks * 2, db + ks * 2, (i | ks) ? 1u : 0u);
            tc_commit(s ? mb1 : mb0);
        }
    }
    mbar_wait(mb1, 1);
    tc_fence_after();
    const int subp = wid & 3, tok = subp * 32 + lane;
    const int cb = (wid >> 2) * 64;
#pragma unroll
    for (int g = 0; g < 2; g++) {
        uint32_t d[32];
        TC_LD32(d, tmem + cb + g * 32);
        tc_wait_ld();
        float o[32];
#pragma unroll
        for (int j = 0; j < 32; j++) {
            int chl = cb + g * 32 + j;
            float vm = __uint_as_float(d[j]) + bsh[chl];
            float cached = sAT[(size_t)ridx[chl] * NTOK + blk * BM_ + tok];
            o[j] = gelu_t(vm) - cached;
        }
        float* dp = g_delta + ((size_t)blk * BM_ + tok) * KSEL + mchunk * 128 + cb + g * 32;
#pragma unroll
        for (int q = 0; q < 8; q++) *(float4*)(dp + q * 4) = *(float4*)&o[q * 4];
    }
    __syncthreads();
    if (wid == 0) tc_dealloc(tmem, 128);

#else
    // fallback: mma.sync, C[ch][tok], delta stored [blk][ch][tok]
    const int G1_ST = 36;
    uint32_t* As = (uint32_t*)base;
    uint32_t* Bs = As + 128 * G1_ST;
    const int wm = wid & 1, wn = wid >> 1;
    const int grp = lane >> 2, tig = lane & 3;

    if (tid < 128) {
        int id = g_inds[blk * KSEL + mchunk * 128 + tid];
        ridx[tid] = id;
        bsh[tid] = fc1b[id];
    }
    __syncthreads();
    float acc[4][4][4];
#pragma unroll
    for (int i = 0; i < 4; i++)
#pragma unroll
        for (int j = 0; j < 4; j++)
#pragma unroll
            for (int q = 0; q < 4; q++) acc[i][j][q] = 0.f;

    const float* xb = x + (size_t)blk * BM_ * C_DIM;
    const int lrow = tid >> 3, lc4 = tid & 7;
    float4 ra[4], rb[4];
#pragma unroll
    for (int r = 0; r < 4; r++) {
        int rrow = lrow + 32 * r;
        ra[r] = *(const float4*)(fc1w + (size_t)ridx[rrow] * C_DIM + lc4 * 4);
        rb[r] = *(const float4*)(xb + (size_t)rrow * C_DIM + lc4 * 4);
    }
    for (int k0 = 0; k0 < C_DIM; k0 += 32) {
#pragma unroll
        for (int r = 0; r < 4; r++) {
            int rrow = lrow + 32 * r;
            int bidx = rrow * G1_ST + lc4 * 4;
            As[bidx + 0] = f2tf(ra[r].x); As[bidx + 1] = f2tf(ra[r].y);
            As[bidx + 2] = f2tf(ra[r].z); As[bidx + 3] = f2tf(ra[r].w);
            Bs[bidx + 0] = f2tf(rb[r].x); Bs[bidx + 1] = f2tf(rb[r].y);
            Bs[bidx + 2] = f2tf(rb[r].z); Bs[bidx + 3] = f2tf(rb[r].w);
        }
        __syncthreads();
        if (k0 + 32 < C_DIM) {
#pragma unroll
            for (int r = 0; r < 4; r++) {
                int rrow = lrow + 32 * r;
                ra[r] = *(const float4*)(fc1w + (size_t)ridx[rrow] * C_DIM + k0 + 32 + lc4 * 4);
                rb[r] = *(const float4*)(xb + (size_t)rrow * C_DIM + k0 + 32 + lc4 * 4);
            }
        }
#pragma unroll
        for (int ks = 0; ks < 4; ks++) {
            const int kk = ks * 8;
            uint32_t af[4][4], bf[4][2];
#pragma unroll
            for (int mt = 0; mt < 4; mt++) {
                int mr = wm * 64 + mt * 16 + grp;
                af[mt][0] = As[mr * G1_ST + kk + tig];
                af[mt][1] = As[(mr + 8) * G1_ST + kk + tig];
                af[mt][2] = As[mr * G1_ST + kk + tig + 4];
                af[mt][3] = As[(mr + 8) * G1_ST + kk + tig + 4];
            }
#pragma unroll
            for (int nt = 0; nt < 4; nt++) {
                int nb = wn * 32 + nt * 8 + grp;
                bf[nt][0] = Bs[nb * G1_ST + kk + tig];
                bf[nt][1] = Bs[nb * G1_ST + kk + tig + 4];
            }
#pragma unroll
            for (int mt = 0; mt < 4; mt++)
#pragma unroll
                for (int nt = 0; nt < 4; nt++) mma_frag(acc[mt][nt], af[mt], bf[nt]);
        }
        __syncthreads();
    }
#pragma unroll
    for (int mt = 0; mt < 4; mt++)
#pragma unroll
        for (int nt = 0; nt < 4; nt++) {
            int t0 = wn * 32 + nt * 8 + tig * 2;
#pragma unroll
            for (int half = 0; half < 2; half++) {
                int r = wm * 64 + mt * 16 + grp + 8 * half;
                float bb = bsh[r];
                int chg = ridx[r];
                const float* cp = sAT + (size_t)chg * NTOK + blk * BM_ + t0;
                float2 cached = *(const float2*)cp;
                float v0 = acc[mt][nt][half * 2 + 0] + bb;
                float v1 = acc[mt][nt][half * 2 + 1] + bb;
                float2 o;
                o.x = gelu_t(v0) - cached.x;
                o.y = gelu_t(v1) - cached.y;
                *(float2*)(g_delta + ((size_t)blk * KSEL + mchunk * 128 + r) * BM_ + t0) = o;
            }
        }
#endif
}

// ---------------- kernel 5: gathered fc2 GEMM + out_cache add ----------------
__global__ __launch_bounds__(256) void k_gemm2(const float* __restrict__ fc2wT,
                                               const float* __restrict__ out_cache,
                                               float* __restrict__ out) {
    extern __shared__ char dsm[];
    char* base = (char*)((((uintptr_t)dsm) + 1023) & ~(uintptr_t)1023);
    __shared__ int kid[KSEL];
    const int tid = threadIdx.x, wid = tid >> 5, lane = tid & 31;
    const int blk = blockIdx.y, n0 = blockIdx.x * 128;

#if TC_OK
    __shared__ uint32_t s_tmem;
    __shared__ uint64_t s_mbar[2];
    const uint32_t sb = sm32(base);

    if (wid == 0) { tc_alloc(sm32(&s_tmem), 128); tc_relinq(); }
    if (tid == 0) { mbar_init(sm32(&s_mbar[0]), 1); mbar_init(sm32(&s_mbar[1]), 1); }
    for (int i = tid; i < KSEL; i += 256) kid[i] = g_inds[blk * KSEL + i];
    __syncthreads();
    const uint32_t tmem = s_tmem;
    const uint32_t mb0 = sm32(&s_mbar[0]), mb1 = sm32(&s_mbar[1]);

    const float* Ab = g_delta + (size_t)blk * BM_ * KSEL;
    const int row = tid >> 3, c4 = tid & 7;
    float4 ra[4];
    float rbv[4][4];
#pragma unroll
    for (int r = 0; r < 4; r++)
        ra[r] = *(const float4*)(Ab + (size_t)(row + 32 * r) * KSEL + c4 * 4);
#pragma unroll
    for (int j = 0; j < 4; j++) {
        int idx = tid + 256 * j;
        int c = idx & 127, ch4 = idx >> 7;
#pragma unroll
        for (int q = 0; q < 4; q++)
            rbv[j][q] = fc2wT[(size_t)kid[ch4 * 4 + q] * C_DIM + n0 + c];
    }
    const int NCH = KSEL / 32;  // 48
    for (int i = 0; i < NCH; i++) {
        const int s = i & 1;
        if (i >= 2) mbar_wait(s ? mb1 : mb0, ((i >> 1) - 1) & 1);
        const uint32_t At = sb + (s * 2 + 0) * 16384, Bt = sb + (s * 2 + 1) * 16384;
#pragma unroll
        for (int r = 0; r < 4; r++) {
            int rr = row + 32 * r;
            uint32_t off = SWZ(rr * 128 + c4 * 16);
            *(float4*)(base + (At - sb) + off) = ra[r];
        }
#pragma unroll
        for (int j = 0; j < 4; j++) {
            int idx = tid + 256 * j;
            int c = idx & 127, ch4 = idx >> 7;
            uint32_t off = SWZ(c * 128 + ch4 * 16);
            *(float4*)(base + (Bt - sb) + off) =
                make_float4(rbv[j][0], rbv[j][1], rbv[j][2], rbv[j][3]);
        }
        fence_async();
        if (i + 1 < NCH) {
            int k0 = (i + 1) * 32;
#pragma unroll
            for (int r = 0; r < 4; r++)
                ra[r] = *(const float4*)(Ab + (size_t)(row + 32 * r) * KSEL + k0 + c4 * 4);
#pragma unroll
            for (int j = 0; j < 4; j++) {
                int idx = tid + 256 * j;
                int c = idx & 127, ch4 = idx >> 7;
#pragma unroll
                for (int q = 0; q < 4; q++)
                    rbv[j][q] = fc2wT[(size_t)kid[k0 + ch4 * 4 + q] * C_DIM + n0 + c];
            }
        }
        __syncthreads();
        if (tid == 0) {
            uint64_t da = mk_desc(At), db = mk_desc(Bt);
#pragma unroll
            for (int ks = 0; ks < 4; ks++)
                mma_ss(tmem, da + ks * 2, db + ks * 2, (i | ks) ? 1u : 0u);
            tc_commit(s ? mb1 : mb0);
        }
    }
    mbar_wait(mb1, 1);
    tc_fence_after();
    const int subp = wid & 3, tok = subp * 32 + lane;
    const int cb = (wid >> 2) * 64;
#pragma unroll
    for (int g = 0; g < 2; g++) {
        uint32_t d[32];
        TC_LD32(d, tmem + cb + g * 32);
        tc_wait_ld();
        size_t off = (size_t)(blk * BM_ + tok) * C_DIM + n0 + cb + g * 32;
#pragma unroll
        for (int q = 0; q < 8; q++) {
            float4 oc = *(const float4*)(out_cache + off + q * 4);
            oc.x += __uint_as_float(d[q * 4 + 0]);
            oc.y += __uint_as_float(d[q * 4 + 1]);
            oc.z += __uint_as_float(d[q * 4 + 2]);
            oc.w += __uint_as_float(d[q * 4 + 3]);
            *(float4*)(out + off + q * 4) = oc;
        }
    }
    __syncthreads();
    if (wid == 0) tc_dealloc(tmem, 128);

#else
    // fallback: mma.sync; A=delta [blk][ch][tok]
    const int G2_ST = 136;
    uint32_t* As = (uint32_t*)base;
    uint32_t* Bs = As + 32 * G2_ST;
    const int wm = wid & 1, wn = wid >> 1;
    const int grp = lane >> 2, tig = lane & 3;

    for (int i = tid; i < KSEL; i += 256) kid[i] = g_inds[blk * KSEL + i];
    __syncthreads();

    float acc[4][4][4];
#pragma unroll
    for (int i = 0; i < 4; i++)
#pragma unroll
        for (int j = 0; j < 4; j++)
#pragma unroll
            for (int q = 0; q < 4; q++) acc[i][j][q] = 0.f;

    const float* Ab = g_delta + (size_t)blk * KSEL * BM_;
    float4 ra[4], rb[4];
#pragma unroll
    for (int r = 0; r < 4; r++) {
        int idx = tid + 256 * r;
        int ch = idx >> 5, t4 = idx & 31;
        ra[r] = *(const float4*)(Ab + (size_t)ch * BM_ + t4 * 4);
        rb[r] = *(const float4*)(fc2wT + (size_t)kid[ch] * C_DIM + n0 + t4 * 4);
    }
    for (int k0 = 0; k0 < KSEL; k0 += 32) {
#pragma unroll
        for (int r = 0; r < 4; r++) {
            int idx = tid + 256 * r;
            int ch = idx >> 5, t4 = idx & 31;
            int bidx = ch * G2_ST + t4 * 4;
            As[bidx + 0] = f2tf(ra[r].x); As[bidx + 1] = f2tf(ra[r].y);
            As[bidx + 2] = f2tf(ra[r].z); As[bidx + 3] = f2tf(ra[r].w);
            Bs[bidx + 0] = f2tf(rb[r].x); Bs[bidx + 1] = f2tf(rb[r].y);
            Bs[bidx + 2] = f2tf(rb[r].z); Bs[bidx + 3] = f2tf(rb[r].w);
        }
        __syncthreads();
        if (k0 + 32 < KSEL) {
#pragma unroll
            for (int r = 0; r < 4; r++) {
                int idx = tid + 256 * r;
                int ch = idx >> 5, t4 = idx & 31;
                ra[r] = *(const float4*)(Ab + (size_t)(k0 + 32 + ch) * BM_ + t4 * 4);
                rb[r] = *(const float4*)(fc2wT + (size_t)kid[k0 + 32 + ch] * C_DIM + n0 + t4 * 4);
            }
        }
#pragma unroll
        for (int ks = 0; ks < 4; ks++) {
            const int kk = ks * 8;
            uint32_t af[4][4], bf[4][2];
#pragma unroll
            for (int mt = 0; mt < 4; mt++) {
                int mbr = wm * 64 + mt * 16 + grp;
                af[mt][0] = As[(kk + tig) * G2_ST + mbr];
                af[mt][1] = As[(kk + tig) * G2_ST + mbr + 8];
                af[mt][2] = As[(kk + tig + 4) * G2_ST + mbr];
                af[mt][3] = As[(kk + tig + 4) * G2_ST + mbr + 8];
            }
#pragma unroll
            for (int nt = 0; nt < 4; nt++) {
                int nb = wn * 32 + nt * 8 + grp;
                bf[nt][0] = Bs[(kk + tig) * G2_ST + nb];
                bf[nt][1] = Bs[(kk + tig + 4) * G2_ST + nb];
            }
#pragma unroll
            for (int mt = 0; mt < 4; mt++)
#pragma unroll
                for (int nt = 0; nt < 4; nt++) mma_frag(acc[mt][nt], af[mt], bf[nt]);
        }
        __syncthreads();
    }
#pragma unroll
    for (int mt = 0; mt < 4; mt++)
#pragma unroll
        for (int nt = 0; nt < 4; nt++) {
            int col = n0 + wn * 32 + nt * 8 + tig * 2;
#pragma unroll
            for (int half = 0; half < 2; half++) {
                int trow = wm * 64 + mt * 16 + grp + 8 * half;
                size_t off = (size_t)(blk * BM_ + trow) * C_DIM + col;
                float2 oc = *(const float2*)(out_cache + off);
                float2 o;
                o.x = oc.x + acc[mt][nt][half * 2 + 0];
                o.y = oc.y + acc[mt][nt][half * 2 + 1];
                *(float2*)(out + off) = o;
            }
        }
#endif
}

// ---------------- launch ----------------
extern "C" void kernel_launch(void* const* d_in, const int* in_sizes, int n_in,
                              void* d_out, int out_size) {
    const float* x     = (const float*)d_in[0];
    const float* fc1w  = (const float*)d_in[1];
    const float* fc1b  = (const float*)d_in[2];
    const float* fc2wT = (const float*)d_in[3];
    const float* bmc   = (const float*)d_in[4];
    const float* sAT   = (const float*)d_in[5];
    const float* outc  = (const float*)d_in[6];
    float* out = (float*)d_out;

    cudaFuncSetAttribute(k_sel,   cudaFuncAttributeMaxDynamicSharedMemorySize, SEL_SMEM);
    cudaFuncSetAttribute(k_gemm1, cudaFuncAttributeMaxDynamicSharedMemorySize, G_SMEM);
    cudaFuncSetAttribute(k_gemm2, cudaFuncAttributeMaxDynamicSharedMemorySize, G_SMEM);

    k_bmean<<<dim3(256, 6), 512>>>(x);
    k_sel<<<dim3(96, 2), 256, SEL_SMEM>>>(fc1w, fc1b, bmc);
    k_topk<<<32, 1024>>>();
    k_gemm1<<<dim3(12, 32), 256, G_SMEM>>>(x, fc1w, fc1b, sAT);
    k_gemm2<<<dim3(24, 32), 256, G_SMEM>>>(fc2wT, outc, out);
}

// round 7
// speedup vs baseline: 1.8123x; 1.0022x over previous
#include <cuda_runtime.h>
#include <cstdint>

#if defined(__CUDA_ARCH_FEAT_SM103_ALL) || defined(__CUDA_ARCH_FEAT_SM100_ALL) || \
    (defined(__CUDA_ARCH_FAMILY_SPECIFIC__) && (__CUDA_ARCH_FAMILY_SPECIFIC__ >= 1000))
#define TC_OK 1
#else
#define TC_OK 0
#endif

#define NTOK 4096
#define C_DIM 3072
#define F_DIM 12288
#define NB 32
#define BM_ 128
#define MBM_ 16
#define MBS 256
#define KSEL 1536

// idesc: dtype F32(1<<4), atype TF32(2<<7), btype TF32(2<<10), N=128(16<<17), M=128(8<<24)
#define IDESC_TF32 ((1u<<4)|(2u<<7)|(2u<<10)|(16u<<17)|(8u<<24))
#define SWZ(o) ((o) ^ (((o) >> 3) & 0x70))

#define SEL_SMEM (8 * 16384 + 1024)
#define G_SMEM   (6 * 16384 + 1024)   // 3 stages x (A 16KB + B 16KB)

// ---------------- scratch ----------------
__device__ float g_bmx[MBS * C_DIM];
__device__ float g_mdiff[NB * F_DIM];
__device__ int   g_inds[NB * KSEL];
__device__ float g_delta[(size_t)NB * BM_ * KSEL];   // [blk][tok][ch], tf32-RNA rounded
__device__ float g_xr[(size_t)NTOK * C_DIM];         // x pre-rounded to tf32-RNA

// ---------------- common helpers ----------------
__device__ __forceinline__ uint32_t f2tf(float x) {
    uint32_t u; asm("cvt.rna.tf32.f32 %0, %1;" : "=r"(u) : "f"(x)); return u;
}
__device__ __forceinline__ float gelu_t(float v) {
    return 0.5f * v * (1.f + tanhf(0.7978845608028654f * (v + 0.044715f * v * v * v)));
}
// legacy mma.sync (fallback path)
__device__ __forceinline__ void mma_frag(float c[4], const uint32_t a[4], const uint32_t b[2]) {
    asm volatile(
        "mma.sync.aligned.m16n8k8.row.col.f32.tf32.tf32.f32 "
        "{%0,%1,%2,%3},{%4,%5,%6,%7},{%8,%9},{%0,%1,%2,%3};"
        : "+f"(c[0]), "+f"(c[1]), "+f"(c[2]), "+f"(c[3])
        : "r"(a[0]), "r"(a[1]), "r"(a[2]), "r"(a[3]), "r"(b[0]), "r"(b[1]));
}

#if TC_OK
// ---------------- tcgen05 + async helpers ----------------
__device__ __forceinline__ uint32_t sm32(const void* p) {
    uint32_t a;
    asm("{ .reg .u64 t; cvta.to.shared.u64 t, %1; cvt.u32.u64 %0, t; }" : "=r"(a) : "l"(p));
    return a;
}
__device__ __forceinline__ void mbar_init(uint32_t m, uint32_t c) {
    asm volatile("mbarrier.init.shared.b64 [%0], %1;" :: "r"(m), "r"(c) : "memory");
}
__device__ __forceinline__ void mbar_wait(uint32_t m, uint32_t par) {
    asm volatile(
        "{\n\t.reg .pred P;\n"
        "W_%=:\n\t"
        "mbarrier.try_wait.parity.acquire.cta.shared::cta.b64 P, [%0], %1, 0x989680;\n\t"
        "@!P bra.uni W_%=;\n\t}"
        :: "r"(m), "r"(par) : "memory");
}
__device__ __forceinline__ void tc_alloc(uint32_t slot, uint32_t n) {
    asm volatile("tcgen05.alloc.cta_group::1.sync.aligned.shared::cta.b32 [%0], %1;"
                 :: "r"(slot), "r"(n) : "memory");
}
__device__ __forceinline__ void tc_relinq() {
    asm volatile("tcgen05.relinquish_alloc_permit.cta_group::1.sync.aligned;");
}
__device__ __forceinline__ void tc_dealloc(uint32_t t, uint32_t n) {
    asm volatile("tcgen05.dealloc.cta_group::1.sync.aligned.b32 %0, %1;" :: "r"(t), "r"(n));
}
__device__ __forceinline__ void tc_commit(uint32_t m) {
    asm volatile("tcgen05.commit.cta_group::1.mbarrier::arrive::one.shared::cluster.b64 [%0];"
                 :: "r"(m) : "memory");
}
__device__ __forceinline__ void fence_async() {
    asm volatile("fence.proxy.async.shared::cta;" ::: "memory");
}
__device__ __forceinline__ void tc_fence_after() {
    asm volatile("tcgen05.fence::after_thread_sync;" ::: "memory");
}
__device__ __forceinline__ void tc_wait_ld() {
    asm volatile("tcgen05.wait::ld.sync.aligned;" ::: "memory");
}
__device__ __forceinline__ void mma_ss(uint32_t d, uint64_t a, uint64_t b, uint32_t en) {
    asm volatile(
        "{\n\t.reg .pred p;\n\t"
        "setp.ne.u32 p, %5, 0;\n\t"
        "tcgen05.mma.cta_group::1.kind::tf32 [%0], %1, %2, %3, {%4,%4,%4,%4}, p;\n\t}"
        :: "r"(d), "l"(a), "l"(b), "r"(IDESC_TF32), "r"(0u), "r"(en) : "memory");
}
__device__ __forceinline__ uint64_t mk_desc(uint32_t addr) {
    const uint64_t base = (uint64_t(2) << 61) | (uint64_t(1) << 46) |
                          (uint64_t(64) << 32) | (uint64_t(1) << 16);
    return base | ((uint64_t)(addr >> 4) & 0x3FFF);
}
__device__ __forceinline__ void cp16(uint32_t dst, const void* src) {
    asm volatile("cp.async.cg.shared.global [%0], [%1], 16;" :: "r"(dst), "l"(src) : "memory");
}
__device__ __forceinline__ void cp4(uint32_t dst, const void* src) {
    asm volatile("cp.async.ca.shared.global [%0], [%1], 4;" :: "r"(dst), "l"(src) : "memory");
}
__device__ __forceinline__ void cp_commit() {
    asm volatile("cp.async.commit_group;" ::: "memory");
}
template <int N>
__device__ __forceinline__ void cp_wait() {
    asm volatile("cp.async.wait_group %0;" :: "n"(N) : "memory");
}
#define TC_LD32(r, a) \
    asm volatile( \
        "tcgen05.ld.sync.aligned.32x32b.x32.b32 " \
        "{%0,%1,%2,%3,%4,%5,%6,%7,%8,%9,%10,%11,%12,%13,%14,%15," \
        "%16,%17,%18,%19,%20,%21,%22,%23,%24,%25,%26,%27,%28,%29,%30,%31}, [%32];" \
        : "=r"((r)[0]),"=r"((r)[1]),"=r"((r)[2]),"=r"((r)[3]),"=r"((r)[4]),"=r"((r)[5]), \
          "=r"((r)[6]),"=r"((r)[7]),"=r"((r)[8]),"=r"((r)[9]),"=r"((r)[10]),"=r"((r)[11]), \
          "=r"((r)[12]),"=r"((r)[13]),"=r"((r)[14]),"=r"((r)[15]),"=r"((r)[16]),"=r"((r)[17]), \
          "=r"((r)[18]),"=r"((r)[19]),"=r"((r)[20]),"=r"((r)[21]),"=r"((r)[22]),"=r"((r)[23]), \
          "=r"((r)[24]),"=r"((r)[25]),"=r"((r)[26]),"=r"((r)[27]),"=r"((r)[28]),"=r"((r)[29]), \
          "=r"((r)[30]),"=r"((r)[31]) : "r"(a))
#endif  // TC_OK

// ---------------- kernel 0: pre-round x to tf32 RNA ----------------
__global__ void k_xr(const float* __restrict__ x) {
    size_t i = (size_t)blockIdx.x * 256 + threadIdx.x;
    float4 v = ((const float4*)x)[i];
    uint4 o;
    asm("cvt.rna.tf32.f32 %0, %1;" : "=r"(o.x) : "f"(v.x));
    asm("cvt.rna.tf32.f32 %0, %1;" : "=r"(o.y) : "f"(v.y));
    asm("cvt.rna.tf32.f32 %0, %1;" : "=r"(o.z) : "f"(v.z));
    asm("cvt.rna.tf32.f32 %0, %1;" : "=r"(o.w) : "f"(v.w));
    ((uint4*)g_xr)[i] = o;
}

// ---------------- kernel 1: block means ----------------
__global__ void k_bmean(const float* __restrict__ x) {
    int mb = blockIdx.x;
    int c  = blockIdx.y * 512 + threadIdx.x;
    const float* p = x + (size_t)mb * MBM_ * C_DIM + c;
    float s = 0.f;
#pragma unroll
    for (int t = 0; t < MBM_; t++) s += p[(size_t)t * C_DIM];
    g_bmx[mb * C_DIM + c] = s * (1.f / 16.f);
}

// ---------------- kernel 2: selection GEMM (3xTF32) fused bias+|diff|+rsum --------------
__global__ __launch_bounds__(256) void k_sel(const float* __restrict__ fc1w,
                                             const float* __restrict__ fc1b,
                                             const float* __restrict__ bmc) {
    extern __shared__ char dsm[];
    char* base = (char*)((((uintptr_t)dsm) + 1023) & ~(uintptr_t)1023);
    const int tid = threadIdx.x, wid = tid >> 5, lane = tid & 31;

#if TC_OK
    __shared__ uint32_t s_tmem;
    __shared__ uint64_t s_mbar[2];
    const int m0 = blockIdx.x * 128, n0 = blockIdx.y * 128;
    const uint32_t sb = sm32(base);

    if (wid == 0) { tc_alloc(sm32(&s_tmem), 128); tc_relinq(); }
    if (tid == 0) { mbar_init(sm32(&s_mbar[0]), 1); mbar_init(sm32(&s_mbar[1]), 1); }
    __syncthreads();
    const uint32_t tmem = s_tmem;
    const uint32_t mb0 = sm32(&s_mbar[0]), mb1 = sm32(&s_mbar[1]);

    const int row = tid >> 3, c4 = tid & 7;
    float4 ra[4], rb[4];
#pragma unroll
    for (int r = 0; r < 4; r++) {
        int rr = row + 32 * r;
        ra[r] = *(const float4*)(fc1w + (size_t)(m0 + rr) * C_DIM + c4 * 4);
        rb[r] = *(const float4*)(g_bmx + (size_t)(n0 + rr) * C_DIM + c4 * 4);
    }
    const int NCH = C_DIM / 32;  // 96
    for (int i = 0; i < NCH; i++) {
        const int s = i & 1;
        if (i >= 2) mbar_wait(s ? mb1 : mb0, ((i >> 1) - 1) & 1);
        const uint32_t Ah = sb + (s * 4 + 0) * 16384, Al = sb + (s * 4 + 1) * 16384;
        const uint32_t Bh = sb + (s * 4 + 2) * 16384, Bl = sb + (s * 4 + 3) * 16384;
#pragma unroll
        for (int r = 0; r < 4; r++) {
            int rr = row + 32 * r;
            uint32_t off = SWZ(rr * 128 + c4 * 16);
            float av[4] = {ra[r].x, ra[r].y, ra[r].z, ra[r].w};
            float bv[4] = {rb[r].x, rb[r].y, rb[r].z, rb[r].w};
            uint4 h, l;
            h.x = f2tf(av[0]); l.x = f2tf(av[0] - __uint_as_float(h.x));
            h.y = f2tf(av[1]); l.y = f2tf(av[1] - __uint_as_float(h.y));
            h.z = f2tf(av[2]); l.z = f2tf(av[2] - __uint_as_float(h.z));
            h.w = f2tf(av[3]); l.w = f2tf(av[3] - __uint_as_float(h.w));
            *(uint4*)(base + (Ah - sb) + off) = h;
            *(uint4*)(base + (Al - sb) + off) = l;
            h.x = f2tf(bv[0]); l.x = f2tf(bv[0] - __uint_as_float(h.x));
            h.y = f2tf(bv[1]); l.y = f2tf(bv[1] - __uint_as_float(h.y));
            h.z = f2tf(bv[2]); l.z = f2tf(bv[2] - __uint_as_float(h.z));
            h.w = f2tf(bv[3]); l.w = f2tf(bv[3] - __uint_as_float(h.w));
            *(uint4*)(base + (Bh - sb) + off) = h;
            *(uint4*)(base + (Bl - sb) + off) = l;
        }
        fence_async();
        if (i + 1 < NCH) {
            int k0 = (i + 1) * 32;
#pragma unroll
            for (int r = 0; r < 4; r++) {
                int rr = row + 32 * r;
                ra[r] = *(const float4*)(fc1w + (size_t)(m0 + rr) * C_DIM + k0 + c4 * 4);
                rb[r] = *(const float4*)(g_bmx + (size_t)(n0 + rr) * C_DIM + k0 + c4 * 4);
            }
        }
        __syncthreads();
        if (tid == 0) {
            uint64_t dah = mk_desc(Ah), dal = mk_desc(Al);
            uint64_t dbh = mk_desc(Bh), dbl = mk_desc(Bl);
#pragma unroll
            for (int ks = 0; ks < 4; ks++) {
                mma_ss(tmem, dah + ks * 2, dbl + ks * 2, (i | ks) ? 1u : 0u);
                mma_ss(tmem, dal + ks * 2, dbh + ks * 2, 1u);
                mma_ss(tmem, dah + ks * 2, dbh + ks * 2, 1u);
            }
            tc_commit(s ? mb1 : mb0);
        }
    }
    mbar_wait(mb1, 1);
    tc_fence_after();
    const int subp = wid & 3, l = subp * 32 + lane;
    const int f = m0 + l;
    const float bias = fc1b[f];
    const int cb = (wid >> 2) * 64;
    float sum[8];
#pragma unroll
    for (int q = 0; q < 8; q++) sum[q] = 0.f;
#pragma unroll
    for (int g = 0; g < 2; g++) {
        uint32_t d[32];
        TC_LD32(d, tmem + cb + g * 32);
        tc_wait_ld();
#pragma unroll
        for (int j = 0; j < 32; j++) {
            int mbi = n0 + cb + g * 32 + j;
            float val = __uint_as_float(d[j]) + bias;
            sum[(g * 32 + j) >> 3] += fabsf(val - bmc[(size_t)mbi * F_DIM + f]);
        }
    }
    const int b0 = (n0 + cb) >> 3;
#pragma unroll
    for (int q = 0; q < 8; q++) g_mdiff[(size_t)(b0 + q) * F_DIM + f] = sum[q];
    __syncthreads();
    if (wid == 0) tc_dealloc(tmem, 128);

#else
    // fallback: mma.sync 3xTF32, C[mb][f], fused mdiff epilogue
    const int SEL_ST = 20;
    uint32_t* Ah = (uint32_t*)base;
    uint32_t* Al = Ah + 128 * SEL_ST;
    uint32_t* Bh = Al + 128 * SEL_ST;
    uint32_t* Bl = Bh + 128 * SEL_ST;
    float* S = (float*)(Bl + 128 * SEL_ST);
    const int m0 = blockIdx.y * 128, n0 = blockIdx.x * 128;
    const int wm = wid & 1, wn = wid >> 1;
    const int grp = lane >> 2, tig = lane & 3;

    float acc[4][4][4];
#pragma unroll
    for (int i = 0; i < 4; i++)
#pragma unroll
        for (int j = 0; j < 4; j++)
#pragma unroll
            for (int q = 0; q < 4; q++) acc[i][j][q] = 0.f;

    float4 ra[2], rb[2];
    const int lrow = tid >> 2, lc4 = tid & 3;
#pragma unroll
    for (int r = 0; r < 2; r++) {
        int rrow = lrow + 64 * r;
        ra[r] = *(const float4*)(g_bmx + (size_t)(m0 + rrow) * C_DIM + lc4 * 4);
        rb[r] = *(const float4*)(fc1w + (size_t)(n0 + rrow) * C_DIM + lc4 * 4);
    }
    for (int k0 = 0; k0 < C_DIM; k0 += 16) {
#pragma unroll
        for (int r = 0; r < 2; r++) {
            int rrow = lrow + 64 * r;
            int bidx = rrow * SEL_ST + lc4 * 4;
            float av[4] = {ra[r].x, ra[r].y, ra[r].z, ra[r].w};
            float bv[4] = {rb[r].x, rb[r].y, rb[r].z, rb[r].w};
#pragma unroll
            for (int i = 0; i < 4; i++) {
                uint32_t h = f2tf(av[i]);
                Ah[bidx + i] = h;
                Al[bidx + i] = f2tf(av[i] - __uint_as_float(h));
                h = f2tf(bv[i]);
                Bh[bidx + i] = h;
                Bl[bidx + i] = f2tf(bv[i] - __uint_as_float(h));
            }
        }
        __syncthreads();
        if (k0 + 16 < C_DIM) {
#pragma unroll
            for (int r = 0; r < 2; r++) {
                int rrow = lrow + 64 * r;
                ra[r] = *(const float4*)(g_bmx + (size_t)(m0 + rrow) * C_DIM + k0 + 16 + lc4 * 4);
                rb[r] = *(const float4*)(fc1w + (size_t)(n0 + rrow) * C_DIM + k0 + 16 + lc4 * 4);
            }
        }
#pragma unroll
        for (int ks = 0; ks < 2; ks++) {
            const int kk = ks * 8;
            uint32_t ah[4][4], al[4][4], bh[4][2], bl[4][2];
#pragma unroll
            for (int mt = 0; mt < 4; mt++) {
                int mr = wm * 64 + mt * 16 + grp;
                ah[mt][0] = Ah[mr * SEL_ST + kk + tig];
                ah[mt][1] = Ah[(mr + 8) * SEL_ST + kk + tig];
                ah[mt][2] = Ah[mr * SEL_ST + kk + tig + 4];
                ah[mt][3] = Ah[(mr + 8) * SEL_ST + kk + tig + 4];
                al[mt][0] = Al[mr * SEL_ST + kk + tig];
                al[mt][1] = Al[(mr + 8) * SEL_ST + kk + tig];
                al[mt][2] = Al[mr * SEL_ST + kk + tig + 4];
                al[mt][3] = Al[(mr + 8) * SEL_ST + kk + tig + 4];
            }
#pragma unroll
            for (int nt = 0; nt < 4; nt++) {
                int nb = wn * 32 + nt * 8 + grp;
                bh[nt][0] = Bh[nb * SEL_ST + kk + tig];
                bh[nt][1] = Bh[nb * SEL_ST + kk + tig + 4];
                bl[nt][0] = Bl[nb * SEL_ST + kk + tig];
                bl[nt][1] = Bl[nb * SEL_ST + kk + tig + 4];
            }
#pragma unroll
            for (int mt = 0; mt < 4; mt++)
#pragma unroll
                for (int nt = 0; nt < 4; nt++) {
                    mma_frag(acc[mt][nt], ah[mt], bl[nt]);
                    mma_frag(acc[mt][nt], al[mt], bh[nt]);
                    mma_frag(acc[mt][nt], ah[mt], bh[nt]);
                }
        }
        __syncthreads();
    }
#pragma unroll
    for (int mt = 0; mt < 4; mt++)
#pragma unroll
        for (int nt = 0; nt < 4; nt++) {
            int m_l = wm * 64 + mt * 16 + grp;
            int n_l = wn * 32 + nt * 8 + tig * 2;
            S[n_l * 129 + m_l]           = acc[mt][nt][0];
            S[(n_l + 1) * 129 + m_l]     = acc[mt][nt][1];
            S[n_l * 129 + m_l + 8]       = acc[mt][nt][2];
            S[(n_l + 1) * 129 + m_l + 8] = acc[mt][nt][3];
        }
    __syncthreads();
    const int f_l = tid & 127, gh = tid >> 7;
    const int fg = n0 + f_l;
    const float bias = fc1b[fg];
#pragma unroll
    for (int q = 0; q < 8; q++) {
        int mb_l0 = (gh * 8 + q) * 8;
        float s = 0.f;
#pragma unroll
        for (int t = 0; t < 8; t++)
            s += fabsf(S[f_l * 129 + mb_l0 + t] + bias -
                       bmc[(size_t)(m0 + mb_l0 + t) * F_DIM + fg]);
        g_mdiff[(size_t)((m0 + mb_l0) >> 3) * F_DIM + fg] = s;
    }
#endif
}

// ---------------- kernel 3: parallel top-1536 (radix select) ----------------
__global__ __launch_bounds__(1024) void k_topk() {
    const int b = blockIdx.x, tid = threadIdx.x;
    const int lane = tid & 31, w = tid >> 5;
    const float* v = g_mdiff + (size_t)b * F_DIM;
    const int f0 = tid * 12;
    float vals[12];
#pragma unroll
    for (int j = 0; j < 12; j++) vals[j] = v[f0 + j];

    __shared__ int hist[256];
    __shared__ unsigned pref_s;
    __shared__ int rem_s;
    __shared__ int wsum[32];
    __shared__ int total_s;

    unsigned pref = 0;
    int rem = KSEL;
    for (int pass = 0; pass < 4; pass++) {
        const int sh = 24 - 8 * pass;
        if (tid < 256) hist[tid] = 0;
        __syncthreads();
#pragma unroll
        for (int j = 0; j < 12; j++) {
            unsigned u = __float_as_uint(vals[j]);
            if (pass == 0 || (u >> (sh + 8)) == pref)
                atomicAdd(&hist[(u >> sh) & 255], 1);
        }
        __syncthreads();
        for (int off = 1; off < 256; off <<= 1) {
            int x_;
            if (tid < 256) x_ = hist[tid] + ((tid + off < 256) ? hist[tid + off] : 0);
            __syncthreads();
            if (tid < 256) hist[tid] = x_;
            __syncthreads();
        }
        if (tid < 256) {
            int nxt = (tid == 255) ? 0 : hist[tid + 1];
            if (hist[tid] >= rem && nxt < rem) {
                pref_s = (pref << 8) | (unsigned)tid;
                rem_s = rem - nxt;
            }
        }
        __syncthreads();
        pref = pref_s;
        rem = rem_s;
        __syncthreads();
    }
    int cgt = 0, ceq = 0;
#pragma unroll
    for (int j = 0; j < 12; j++) {
        unsigned u = __float_as_uint(vals[j]);
        if (u > pref) cgt++;
        else if (u == pref) ceq++;
    }
    int inc = cgt;
#pragma unroll
    for (int off = 1; off < 32; off <<= 1) {
        int n_ = __shfl_up_sync(0xffffffffu, inc, off);
        if (lane >= off) inc += n_;
    }
    if (lane == 31) wsum[w] = inc;
    __syncthreads();
    if (w == 0) {
        int t = wsum[lane];
#pragma unroll
        for (int off = 1; off < 32; off <<= 1) {
            int n_ = __shfl_up_sync(0xffffffffu, t, off);
            if (lane >= off) t += n_;
        }
        wsum[lane] = t;
    }
    __syncthreads();
    int basep = (w > 0 ? wsum[w - 1] : 0) + inc - cgt;
    if (tid == 1023) total_s = basep + cgt;
    __syncthreads();
    const int total_gt = total_s;
    {
        int pos = basep;
#pragma unroll
        for (int j = 0; j < 12; j++)
            if (__float_as_uint(vals[j]) > pref) g_inds[b * KSEL + (pos++)] = f0 + j;
    }
    __syncthreads();
    inc = ceq;
#pragma unroll
    for (int off = 1; off < 32; off <<= 1) {
        int n_ = __shfl_up_sync(0xffffffffu, inc, off);
        if (lane >= off) inc += n_;
    }
    if (lane == 31) wsum[w] = inc;
    __syncthreads();
    if (w == 0) {
        int t = wsum[lane];
#pragma unroll
        for (int off = 1; off < 32; off <<= 1) {
            int n_ = __shfl_up_sync(0xffffffffu, t, off);
            if (lane >= off) t += n_;
        }
        wsum[lane] = t;
    }
    __syncthreads();
    int ebase = (w > 0 ? wsum[w - 1] : 0) + inc - ceq;
    const int need = KSEL - total_gt;
#pragma unroll
    for (int j = 0; j < 12; j++)
        if (__float_as_uint(vals[j]) == pref) {
            if (ebase < need) g_inds[b * KSEL + total_gt + ebase] = f0 + j;
            ebase++;
        }
}

// ---------------- kernel 4: gathered fc1 GEMM + gelu + delta (cp.async 3-stage) ---------
__global__ __launch_bounds__(256) void k_gemm1(const float* __restrict__ x,
                                               const float* __restrict__ fc1w,
                                               const float* __restrict__ fc1b,
                                               const float* __restrict__ sAT) {
    extern __shared__ char dsm[];
    char* base = (char*)((((uintptr_t)dsm) + 1023) & ~(uintptr_t)1023);
    __shared__ int ridx[128];
    __shared__ float bsh[128];
    const int tid = threadIdx.x, wid = tid >> 5, lane = tid & 31;
    const int blk = blockIdx.y, mchunk = blockIdx.x;

#if TC_OK
    __shared__ uint32_t s_tmem;
    __shared__ uint64_t s_mbar[3];
    const uint32_t sb = sm32(base);

    if (wid == 0) { tc_alloc(sm32(&s_tmem), 128); tc_relinq(); }
    if (tid == 0)
        for (int q = 0; q < 3; q++) mbar_init(sm32(&s_mbar[q]), 1);
    if (tid < 128) {
        int id = g_inds[blk * KSEL + mchunk * 128 + tid];
        ridx[tid] = id;
        bsh[tid] = fc1b[id];
    }
    __syncthreads();
    const uint32_t tmem = s_tmem;
    uint32_t mbx[3] = {sm32(&s_mbar[0]), sm32(&s_mbar[1]), sm32(&s_mbar[2])};

    const float* xb = g_xr + (size_t)blk * BM_ * C_DIM;
    const int row = tid >> 3, c4 = tid & 7;
    const uint32_t swoff = SWZ(row * 128 + c4 * 16);

    const int NCH = C_DIM / 32;  // 96
    // prologue: stages 0..2
#pragma unroll
    for (int j = 0; j < 3; j++) {
        const uint32_t At = sb + (j * 2 + 0) * 16384, Bt = sb + (j * 2 + 1) * 16384;
        int k0 = j * 32;
#pragma unroll
        for (int r = 0; r < 4; r++) {
            int rr = row + 32 * r;
            cp16(At + SWZ(rr * 128 + c4 * 16), xb + (size_t)rr * C_DIM + k0 + c4 * 4);
            cp16(Bt + SWZ(rr * 128 + c4 * 16), fc1w + (size_t)ridx[rr] * C_DIM + k0 + c4 * 4);
        }
        cp_commit();
    }
    for (int i = 0; i < NCH; i++) {
        const int b = i % 3;
        if (i < NCH - 2)      cp_wait<2>();
        else if (i == NCH - 2) cp_wait<1>();
        else                   cp_wait<0>();
        fence_async();
        __syncthreads();
        const uint32_t At = sb + (b * 2 + 0) * 16384, Bt = sb + (b * 2 + 1) * 16384;
        if (tid == 0) {
            uint64_t da = mk_desc(At), db = mk_desc(Bt);
#pragma unroll
            for (int ks = 0; ks < 4; ks++)
                mma_ss(tmem, da + ks * 2, db + ks * 2, (i | ks) ? 1u : 0u);
            tc_commit(mbx[b]);
        }
        if (i + 3 < NCH) {
            mbar_wait(mbx[b], (i / 3) & 1);   // mma of chunk i done -> buffer free
            int k0 = (i + 3) * 32;
#pragma unroll
            for (int r = 0; r < 4; r++) {
                int rr = row + 32 * r;
                cp16(At + SWZ(rr * 128 + c4 * 16), xb + (size_t)rr * C_DIM + k0 + c4 * 4);
                cp16(Bt + SWZ(rr * 128 + c4 * 16), fc1w + (size_t)ridx[rr] * C_DIM + k0 + c4 * 4);
            }
            cp_commit();
        }
    }
    mbar_wait(mbx[(NCH - 1) % 3], ((NCH - 1) / 3) & 1);
    tc_fence_after();
    const int subp = wid & 3, tok = subp * 32 + lane;
    const int cb = (wid >> 2) * 64;
#pragma unroll
    for (int g = 0; g < 2; g++) {
        uint32_t d[32];
        TC_LD32(d, tmem + cb + g * 32);
        tc_wait_ld();
        uint32_t o[32];
#pragma unroll
        for (int j = 0; j < 32; j++) {
            int chl = cb + g * 32 + j;
            float vm = __uint_as_float(d[j]) + bsh[chl];
            float cached = sAT[(size_t)ridx[chl] * NTOK + blk * BM_ + tok];
            o[j] = f2tf(gelu_t(vm) - cached);   // RNA-round delta for gemm2
        }
        float* dp = g_delta + ((size_t)blk * BM_ + tok) * KSEL + mchunk * 128 + cb + g * 32;
#pragma unroll
        for (int q = 0; q < 8; q++) *(uint4*)(dp + q * 4) = *(uint4*)&o[q * 4];
    }
    __syncthreads();
    if (wid == 0) tc_dealloc(tmem, 128);

#else
    // fallback: mma.sync, C[ch][tok], delta stored [blk][ch][tok]
    const int G1_ST = 36;
    uint32_t* As = (uint32_t*)base;
    uint32_t* Bs = As + 128 * G1_ST;
    const int wm = wid & 1, wn = wid >> 1;
    const int grp = lane >> 2, tig = lane & 3;

    if (tid < 128) {
        int id = g_inds[blk * KSEL + mchunk * 128 + tid];
        ridx[tid] = id;
        bsh[tid] = fc1b[id];
    }
    __syncthreads();
    float acc[4][4][4];
#pragma unroll
    for (int i = 0; i < 4; i++)
#pragma unroll
        for (int j = 0; j < 4; j++)
#pragma unroll
            for (int q = 0; q < 4; q++) acc[i][j][q] = 0.f;

    const float* xb = x + (size_t)blk * BM_ * C_DIM;
    const int lrow = tid >> 3, lc4 = tid & 7;
    float4 ra[4], rb[4];
#pragma unroll
    for (int r = 0; r < 4; r++) {
        int rrow = lrow + 32 * r;
        ra[r] = *(const float4*)(fc1w + (size_t)ridx[rrow] * C_DIM + lc4 * 4);
        rb[r] = *(const float4*)(xb + (size_t)rrow * C_DIM + lc4 * 4);
    }
    for (int k0 = 0; k0 < C_DIM; k0 += 32) {
#pragma unroll
        for (int r = 0; r < 4; r++) {
            int rrow = lrow + 32 * r;
            int bidx = rrow * G1_ST + lc4 * 4;
            As[bidx + 0] = f2tf(ra[r].x); As[bidx + 1] = f2tf(ra[r].y);
            As[bidx + 2] = f2tf(ra[r].z); As[bidx + 3] = f2tf(ra[r].w);
            Bs[bidx + 0] = f2tf(rb[r].x); Bs[bidx + 1] = f2tf(rb[r].y);
            Bs[bidx + 2] = f2tf(rb[r].z); Bs[bidx + 3] = f2tf(rb[r].w);
        }
        __syncthreads();
        if (k0 + 32 < C_DIM) {
#pragma unroll
            for (int r = 0; r < 4; r++) {
                int rrow = lrow + 32 * r;
                ra[r] = *(const float4*)(fc1w + (size_t)ridx[rrow] * C_DIM + k0 + 32 + lc4 * 4);
                rb[r] = *(const float4*)(xb + (size_t)rrow * C_DIM + k0 + 32 + lc4 * 4);
            }
        }
#pragma unroll
        for (int ks = 0; ks < 4; ks++) {
            const int kk = ks * 8;
            uint32_t af[4][4], bf[4][2];
#pragma unroll
            for (int mt = 0; mt < 4; mt++) {
                int mr = wm * 64 + mt * 16 + grp;
                af[mt][0] = As[mr * G1_ST + kk + tig];
                af[mt][1] = As[(mr + 8) * G1_ST + kk + tig];
                af[mt][2] = As[mr * G1_ST + kk + tig + 4];
                af[mt][3] = As[(mr + 8) * G1_ST + kk + tig + 4];
            }
#pragma unroll
            for (int nt = 0; nt < 4; nt++) {
                int nb = wn * 32 + nt * 8 + grp;
                bf[nt][0] = Bs[nb * G1_ST + kk + tig];
                bf[nt][1] = Bs[nb * G1_ST + kk + tig + 4];
            }
#pragma unroll
            for (int mt = 0; mt < 4; mt++)
#pragma unroll
                for (int nt = 0; nt < 4; nt++) mma_frag(acc[mt][nt], af[mt], bf[nt]);
        }
        __syncthreads();
    }
#pragma unroll
    for (int mt = 0; mt < 4; mt++)
#pragma unroll
        for (int nt = 0; nt < 4; nt++) {
            int t0 = wn * 32 + nt * 8 + tig * 2;
#pragma unroll
            for (int half = 0; half < 2; half++) {
                int r = wm * 64 + mt * 16 + grp + 8 * half;
                float bb = bsh[r];
                int chg = ridx[r];
                const float* cp = sAT + (size_t)chg * NTOK + blk * BM_ + t0;
                float2 cached = *(const float2*)cp;
                float v0 = acc[mt][nt][half * 2 + 0] + bb;
                float v1 = acc[mt][nt][half * 2 + 1] + bb;
                float2 o;
                o.x = gelu_t(v0) - cached.x;
                o.y = gelu_t(v1) - cached.y;
                *(float2*)(g_delta + ((size_t)blk * KSEL + mchunk * 128 + r) * BM_ + t0) = o;
            }
        }
#endif
}

// ---------------- kernel 5: gathered fc2 GEMM + out_cache add (cp.async 3-stage) --------
__global__ __launch_bounds__(256) void k_gemm2(const float* __restrict__ fc2wT,
                                               const float* __restrict__ out_cache,
                                               float* __restrict__ out) {
    extern __shared__ char dsm[];
    char* base = (char*)((((uintptr_t)dsm) + 1023) & ~(uintptr_t)1023);
    __shared__ int kid[KSEL];
    const int tid = threadIdx.x, wid = tid >> 5, lane = tid & 31;
    const int blk = blockIdx.y, n0 = blockIdx.x * 128;

#if TC_OK
    __shared__ uint32_t s_tmem;
    __shared__ uint64_t s_mbar[3];
    const uint32_t sb = sm32(base);

    if (wid == 0) { tc_alloc(sm32(&s_tmem), 128); tc_relinq(); }
    if (tid == 0)
        for (int q = 0; q < 3; q++) mbar_init(sm32(&s_mbar[q]), 1);
    for (int i = tid; i < KSEL; i += 256) kid[i] = g_inds[blk * KSEL + i];
    __syncthreads();
    const uint32_t tmem = s_tmem;
    uint32_t mbx[3] = {sm32(&s_mbar[0]), sm32(&s_mbar[1]), sm32(&s_mbar[2])};

    const float* Ab = g_delta + (size_t)blk * BM_ * KSEL;
    const int row = tid >> 3, c4 = tid & 7;
    const int cB = tid & 127, ch4b = tid >> 7;   // B transpose mapping base

    const int NCH = KSEL / 32;  // 48
#pragma unroll
    for (int j = 0; j < 3; j++) {
        const uint32_t At = sb + (j * 2 + 0) * 16384, Bt = sb + (j * 2 + 1) * 16384;
        int k0 = j * 32;
#pragma unroll
        for (int r = 0; r < 4; r++) {
            int rr = row + 32 * r;
            cp16(At + SWZ(rr * 128 + c4 * 16), Ab + (size_t)rr * KSEL + k0 + c4 * 4);
        }
#pragma unroll
        for (int jj = 0; jj < 4; jj++) {
            int ch4 = ch4b + jj * 2;   // 0..7
            uint32_t db = Bt + SWZ(cB * 128 + ch4 * 16);
#pragma unroll
            for (int q = 0; q < 4; q++)
                cp4(db + q * 4, fc2wT + (size_t)kid[k0 + ch4 * 4 + q] * C_DIM + n0 + cB);
        }
        cp_commit();
    }
    for (int i = 0; i < NCH; i++) {
        const int b = i % 3;
        if (i < NCH - 2)      cp_wait<2>();
        else if (i == NCH - 2) cp_wait<1>();
        else                   cp_wait<0>();
        fence_async();
        __syncthreads();
        const uint32_t At = sb + (b * 2 + 0) * 16384, Bt = sb + (b * 2 + 1) * 16384;
        if (tid == 0) {
            uint64_t da = mk_desc(At), db = mk_desc(Bt);
#pragma unroll
            for (int ks = 0; ks < 4; ks++)
                mma_ss(tmem, da + ks * 2, db + ks * 2, (i | ks) ? 1u : 0u);
            tc_commit(mbx[b]);
        }
        if (i + 3 < NCH) {
            mbar_wait(mbx[b], (i / 3) & 1);
            int k0 = (i + 3) * 32;
#pragma unroll
            for (int r = 0; r < 4; r++) {
                int rr = row + 32 * r;
                cp16(At + SWZ(rr * 128 + c4 * 16), Ab + (size_t)rr * KSEL + k0 + c4 * 4);
            }
#pragma unroll
            for (int jj = 0; jj < 4; jj++) {
                int ch4 = ch4b + jj * 2;
                uint32_t db = Bt + SWZ(cB * 128 + ch4 * 16);
#pragma unroll
                for (int q = 0; q < 4; q++)
                    cp4(db + q * 4, fc2wT + (size_t)kid[k0 + ch4 * 4 + q] * C_DIM + n0 + cB);
            }
            cp_commit();
        }
    }
    mbar_wait(mbx[(NCH - 1) % 3], ((NCH - 1) / 3) & 1);
    tc_fence_after();
    const int subp = wid & 3, tok = subp * 32 + lane;
    const int cb = (wid >> 2) * 64;
#pragma unroll
    for (int g = 0; g < 2; g++) {
        uint32_t d[32];
        TC_LD32(d, tmem + cb + g * 32);
        tc_wait_ld();
        size_t off = (size_t)(blk * BM_ + tok) * C_DIM + n0 + cb + g * 32;
#pragma unroll
        for (int q = 0; q < 8; q++) {
            float4 oc = *(const float4*)(out_cache + off + q * 4);
            oc.x += __uint_as_float(d[q * 4 + 0]);
            oc.y += __uint_as_float(d[q * 4 + 1]);
            oc.z += __uint_as_float(d[q * 4 + 2]);
            oc.w += __uint_as_float(d[q * 4 + 3]);
            *(float4*)(out + off + q * 4) = oc;
        }
    }
    __syncthreads();
    if (wid == 0) tc_dealloc(tmem, 128);

#else
    // fallback: mma.sync; A=delta [blk][ch][tok]
    const int G2_ST = 136;
    uint32_t* As = (uint32_t*)base;
    uint32_t* Bs = As + 32 * G2_ST;
    const int wm = wid & 1, wn = wid >> 1;
    const int grp = lane >> 2, tig = lane & 3;

    for (int i = tid; i < KSEL; i += 256) kid[i] = g_inds[blk * KSEL + i];
    __syncthreads();

    float acc[4][4][4];
#pragma unroll
    for (int i = 0; i < 4; i++)
#pragma unroll
        for (int j = 0; j < 4; j++)
#pragma unroll
            for (int q = 0; q < 4; q++) acc[i][j][q] = 0.f;

    const float* Ab = g_delta + (size_t)blk * KSEL * BM_;
    float4 ra[4], rb[4];
#pragma unroll
    for (int r = 0; r < 4; r++) {
        int idx = tid + 256 * r;
        int ch = idx >> 5, t4 = idx & 31;
        ra[r] = *(const float4*)(Ab + (size_t)ch * BM_ + t4 * 4);
        rb[r] = *(const float4*)(fc2wT + (size_t)kid[ch] * C_DIM + n0 + t4 * 4);
    }
    for (int k0 = 0; k0 < KSEL; k0 += 32) {
#pragma unroll
        for (int r = 0; r < 4; r++) {
            int idx = tid + 256 * r;
            int ch = idx >> 5, t4 = idx & 31;
            int bidx = ch * G2_ST + t4 * 4;
            As[bidx + 0] = f2tf(ra[r].x); As[bidx + 1] = f2tf(ra[r].y);
            As[bidx + 2] = f2tf(ra[r].z); As[bidx + 3] = f2tf(ra[r].w);
            Bs[bidx + 0] = f2tf(rb[r].x); Bs[bidx + 1] = f2tf(rb[r].y);
            Bs[bidx + 2] = f2tf(rb[r].z); Bs[bidx + 3] = f2tf(rb[r].w);
        }
        __syncthreads();
        if (k0 + 32 < KSEL) {
#pragma unroll
            for (int r = 0; r < 4; r++) {
                int idx = tid + 256 * r;
                int ch = idx >> 5, t4 = idx & 31;
                ra[r] = *(const float4*)(Ab + (size_t)(k0 + 32 + ch) * BM_ + t4 * 4);
                rb[r] = *(const float4*)(fc2wT + (size_t)kid[k0 + 32 + ch] * C_DIM + n0 + t4 * 4);
            }
        }
#pragma unroll
        for (int ks = 0; ks < 4; ks++) {
            const int kk = ks * 8;
            uint32_t af[4][4], bf[4][2];
#pragma unroll
            for (int mt = 0; mt < 4; mt++) {
                int mbr = wm * 64 + mt * 16 + grp;
                af[mt][0] = As[(kk + tig) * G2_ST + mbr];
                af[mt][1] = As[(kk + tig) * G2_ST + mbr + 8];
                af[mt][2] = As[(kk + tig + 4) * G2_ST + mbr];
                af[mt][3] = As[(kk + tig + 4) * G2_ST + mbr + 8];
            }
#pragma unroll
            for (int nt = 0; nt < 4; nt++) {
                int nb = wn * 32 + nt * 8 + grp;
                bf[nt][0] = Bs[(kk + tig) * G2_ST + nb];
                bf[nt][1] = Bs[(kk + tig + 4) * G2_ST + nb];
            }
#pragma unroll
            for (int mt = 0; mt < 4; mt++)
#pragma unroll
                for (int nt = 0; nt < 4; nt++) mma_frag(acc[mt][nt], af[mt], bf[nt]);
        }
        __syncthreads();
    }
#pragma unroll
    for (int mt = 0; mt < 4; mt++)
#pragma unroll
        for (int nt = 0; nt < 4; nt++) {
            int col = n0 + wn * 32 + nt * 8 + tig * 2;
#pragma unroll
            for (int half = 0; half < 2; half++) {
                int trow = wm * 64 + mt * 16 + grp + 8 * half;
                size_t off = (size_t)(blk * BM_ + trow) * C_DIM + col;
                float2 oc = *(const float2*)(out_cache + off);
                float2 o;
                o.x = oc.x + acc[mt][nt][half * 2 + 0];
                o.y = oc.y + acc[mt][nt][half * 2 + 1];
                *(float2*)(out + off) = o;
            }
        }
#endif
}

// ---------------- launch ----------------
extern "C" void kernel_launch(void* const* d_in, const int* in_sizes, int n_in,
                              void* d_out, int out_size) {
    const float* x     = (const float*)d_in[0];
    const float* fc1w  = (const float*)d_in[1];
    const float* fc1b  = (const float*)d_in[2];
    const float* fc2wT = (const float*)d_in[3];
    const float* bmc   = (const float*)d_in[4];
    const float* sAT   = (const float*)d_in[5];
    const float* outc  = (const float*)d_in[6];
    float* out = (float*)d_out;

    cudaFuncSetAttribute(k_sel,   cudaFuncAttributeMaxDynamicSharedMemorySize, SEL_SMEM);
    cudaFuncSetAttribute(k_gemm1, cudaFuncAttributeMaxDynamicSharedMemorySize, G_SMEM);
    cudaFuncSetAttribute(k_gemm2, cudaFuncAttributeMaxDynamicSharedMemorySize, G_SMEM);

    k_xr<<<NTOK * C_DIM / 1024, 256>>>(x);
    k_bmean<<<dim3(256, 6), 512>>>(x);
    k_sel<<<dim3(96, 2), 256, SEL_SMEM>>>(fc1w, fc1b, bmc);
    k_topk<<<32, 1024>>>();
    k_gemm1<<<dim3(12, 32), 256, G_SMEM>>>(x, fc1w, fc1b, sAT);
    k_gemm2<<<dim3(24, 32), 256, G_SMEM>>>(fc2wT, outc, out);
}